// round 11
// baseline (speedup 1.0000x reference)
#include <cuda_runtime.h>
#include <cuda_fp16.h>
#include <math.h>
#include <stdint.h>

#define TT 128
#define BB 256
#define DD 512
#define HH 1024
#define GG 4096   // 4*H

// ===================== scratch (static device globals) ======================
__device__ __align__(16) __half g_inc [(size_t)8  * 32768 * 64]; // inputs hi (C=8)
__device__ __align__(16) __half g_xc  [(size_t)16 * 32768 * 64]; // x hi      (C=16)
__device__ __align__(16) __half g_w1c [(size_t)8  * 1024  * 64]; // W1 hi
__device__ __align__(16) __half g_wihc[(size_t)16 * 4096  * 64]; // W_ih hi (gate-perm)
__device__ __align__(16) __half g_whhc[(size_t)16 * 4096  * 64]; // W_hh hi (gate-perm)
#define HSPLIT ((size_t)16 * 256 * 64)
__device__ __align__(16) __half g_hc  [2 * HSPLIT];              // h hi, ping-pong
__device__ __align__(16) float g_xg[(size_t)TT * BB * GG];       // gate-perm cols
__device__ __align__(16) float g_bias[GG];                       // gate-perm
__device__ int g_prog[2][16];                                    // per (m-group, h-chunk) progress

// ===================== PTX helpers ==========================================
__device__ __forceinline__ uint32_t smem_u32(const void* p) {
    return (uint32_t)__cvta_generic_to_shared(p);
}
__device__ __forceinline__ void cp_async16(uint32_t dst, const void* src) {
    asm volatile("cp.async.cg.shared.global [%0], [%1], 16;" :: "r"(dst), "l"(src));
}
__device__ __forceinline__ void cp_commit() {
    asm volatile("cp.async.commit_group;" ::: "memory");
}
template<int N>
__device__ __forceinline__ void cp_wait() {
    asm volatile("cp.async.wait_group %0;" :: "n"(N) : "memory");
}
__device__ __forceinline__ void ldsm_x4(uint32_t& r0, uint32_t& r1, uint32_t& r2, uint32_t& r3,
                                        uint32_t addr) {
    asm volatile("ldmatrix.sync.aligned.m8n8.x4.shared.b16 {%0,%1,%2,%3}, [%4];"
                 : "=r"(r0), "=r"(r1), "=r"(r2), "=r"(r3) : "r"(addr));
}
__device__ __forceinline__ void mma16816(float* c, const uint32_t* a, const uint32_t* b) {
    asm volatile(
        "mma.sync.aligned.m16n8k16.row.col.f32.f16.f16.f32 "
        "{%0,%1,%2,%3}, {%4,%5,%6,%7}, {%8,%9}, {%0,%1,%2,%3};"
        : "+f"(c[0]), "+f"(c[1]), "+f"(c[2]), "+f"(c[3])
        : "r"(a[0]), "r"(a[1]), "r"(a[2]), "r"(a[3]), "r"(b[0]), "r"(b[1]));
}

__device__ __forceinline__ void store_hi(__half* dst, int M, int m, int n, float v) {
    const int chunk = n >> 6, col = n & 63;
    dst[((size_t)chunk * M + m) * 64 + col] = __float2half_rn(v);
}

// chunk loader: A tile RA rows, B tile RB rows, 128B rows, XOR-swizzled
#define LOAD_CHUNK(A_, B_, M_, N_, mB_, nB_, RA_, RB_, ac_, bc_, dA_)             \
    do {                                                                          \
        const char* As_ = (const char*)((A_) + ((size_t)(ac_) * (M_) + (mB_)) * 64);\
        const char* Bs_ = (const char*)((B_) + ((size_t)(bc_) * (N_) + (nB_)) * 64);\
        const uint32_t dB_ = (dA_) + (RA_) * 128u;                                \
        _Pragma("unroll")                                                         \
        for (int q_ = 0; q_ < (RA_) / 32; q_++) {                                 \
            const int e_ = tid + q_ * 256;                                        \
            const int r_ = e_ >> 3, s_ = e_ & 7;                                  \
            const uint32_t off_ = r_ * 128 + (((uint32_t)(s_ ^ (r_ & 7))) << 4);  \
            cp_async16((dA_) + off_, As_ + r_ * 128 + s_ * 16);                   \
        }                                                                         \
        _Pragma("unroll")                                                         \
        for (int q_ = 0; q_ < (RB_) / 32; q_++) {                                 \
            const int e_ = tid + q_ * 256;                                        \
            const int r_ = e_ >> 3, s_ = e_ & 7;                                  \
            const uint32_t off_ = r_ * 128 + (((uint32_t)(s_ ^ (r_ & 7))) << 4);  \
            cp_async16(dB_ + off_, Bs_ + r_ * 128 + s_ * 16);                     \
        }                                                                         \
    } while (0)

// A-only loader (128 rows)
#define LOAD_A(A_, mB_, ac_, dA_)                                                 \
    do {                                                                          \
        const char* As_ = (const char*)((A_) + ((size_t)(ac_) * 256 + (mB_)) * 64);\
        _Pragma("unroll")                                                         \
        for (int q_ = 0; q_ < 4; q_++) {                                          \
            const int e_ = tid + q_ * 256;                                        \
            const int r_ = e_ >> 3, s_ = e_ & 7;                                  \
            const uint32_t off_ = r_ * 128 + (((uint32_t)(s_ ^ (r_ & 7))) << 4);  \
            cp_async16((dA_) + off_, As_ + r_ * 128 + s_ * 16);                   \
        }                                                                         \
    } while (0)

// ===================== big GEMMs (BM=BN=128, 1-pass fp16, 2 CTA/SM) ==========
// MODE 0: v=relu(v+aux[n]) -> hi store; MODE 1: v=v+aux[n] -> outF
template<int MODE>
__global__ __launch_bounds__(256, 2)
void gemm_mma(const __half* __restrict__ A, const __half* __restrict__ B,
              const float* __restrict__ aux, float* __restrict__ outF,
              __half* __restrict__ outSplit, int M, int N, int C)
{
    extern __shared__ char smraw[];
    const uint32_t sbase = smem_u32(smraw);

    const int tid  = threadIdx.x;
    const int lane = tid & 31;
    const int wid  = tid >> 5;
    const int wm   = wid & 3;
    const int wn   = wid >> 2;
    const int mBase = blockIdx.y * 128;
    const int nBase = blockIdx.x * 128;
    const int NIT = C;

    float c[2][8][4];
#pragma unroll
    for (int i = 0; i < 2; i++)
#pragma unroll
        for (int j = 0; j < 8; j++)
#pragma unroll
            for (int k = 0; k < 4; k++) c[i][j][k] = 0.0f;

    const int lrow_a = ((lane >> 3) & 1) * 8 + (lane & 7);
    const int lrow_b = (lane >> 4) * 8 + (lane & 7);
    const int lxor   = lane & 7;
    const int ahalf  = lane >> 4;
    const int bhalf  = (lane >> 3) & 1;

    LOAD_CHUNK(A, B, M, N, mBase, nBase, 128, 128, 0, 0, sbase);
    cp_commit();

    for (int i = 0; i < NIT; i++) {
        const int buf = i & 1;
        if (i + 1 < NIT) {
            LOAD_CHUNK(A, B, M, N, mBase, nBase, 128, 128, i + 1, i + 1,
                       sbase + ((i + 1) & 1) * 32768u);
            cp_commit();
            cp_wait<1>();
        } else {
            cp_wait<0>();
        }
        __syncthreads();

        const uint32_t aTile = sbase + buf * 32768u;
        const uint32_t bTile = aTile + 16384u;
#pragma unroll
        for (int kk = 0; kk < 4; kk++) {
            uint32_t a[2][4], b[8][2];
#pragma unroll
            for (int mt = 0; mt < 2; mt++) {
                const int row = wm * 32 + mt * 16 + lrow_a;
                const uint32_t addr = aTile + row * 128 +
                    (((uint32_t)((kk * 2 + ahalf) ^ lxor)) << 4);
                ldsm_x4(a[mt][0], a[mt][1], a[mt][2], a[mt][3], addr);
            }
#pragma unroll
            for (int bt = 0; bt < 4; bt++) {
                const int row = wn * 64 + bt * 16 + lrow_b;
                const uint32_t addr = bTile + row * 128 +
                    (((uint32_t)((kk * 2 + bhalf) ^ lxor)) << 4);
                uint32_t r0, r1, r2, r3;
                ldsm_x4(r0, r1, r2, r3, addr);
                b[2 * bt][0] = r0;     b[2 * bt][1] = r1;
                b[2 * bt + 1][0] = r2; b[2 * bt + 1][1] = r3;
            }
#pragma unroll
            for (int mt = 0; mt < 2; mt++)
#pragma unroll
                for (int nt = 0; nt < 8; nt++)
                    mma16816(c[mt][nt], a[mt], b[nt]);
        }
        __syncthreads();
    }

    const int g  = lane >> 2;
    const int tg = lane & 3;
#pragma unroll
    for (int mt = 0; mt < 2; mt++) {
        const int m0 = mBase + wm * 32 + mt * 16 + g;
#pragma unroll
        for (int nt = 0; nt < 8; nt++) {
            const int n0 = nBase + wn * 64 + nt * 8 + tg * 2;
#pragma unroll
            for (int half = 0; half < 2; half++) {
                const int m = m0 + half * 8;
                const float v0 = c[mt][nt][half * 2 + 0];
                const float v1 = c[mt][nt][half * 2 + 1];
                if (MODE == 0) {
                    store_hi(outSplit, M, m, n0,     fmaxf(v0 + aux[n0],     0.0f));
                    store_hi(outSplit, M, m, n0 + 1, fmaxf(v1 + aux[n0 + 1], 0.0f));
                } else {
                    float2 r = make_float2(v0 + aux[n0], v1 + aux[n0 + 1]);
                    *(float2*)(outF + (size_t)m * N + n0) = r;
                }
            }
        }
    }
}

// ===================== persistent fused recurrence ===========================
// W_hh resident in smem; barrier-free chunk-flag pipeline.
// smem layout: [0,128K) W chunks | [128K,160K) A dbl-buf | [160K,+34.8K) gates
#define GATE_W 68
#define SM_W    0u
#define SM_A    131072u
#define SM_GATE 163840u
#define SMEM_REC (163840 + 128 * GATE_W * 4)

__device__ __forceinline__ float sigf(float x) { return 1.0f / (1.0f + __expf(-x)); }

__device__ __forceinline__ void wait_flag(const int* f, int target) {
    volatile const int* vf = f;
    while (*vf < target) __nanosleep(40);
    __threadfence();   // acquire: order producer h-stores before our cp.async reads
}

__global__ __launch_bounds__(256, 1)
void rec_persist_k(__half* __restrict__ hc0, __half* __restrict__ hc1,
                   const __half* __restrict__ whh, const float* __restrict__ xg,
                   const float* __restrict__ W_out, const float* __restrict__ c0,
                   float* __restrict__ out, float* __restrict__ hT, float* __restrict__ cT)
{
    extern __shared__ char smraw[];
    const uint32_t sbase = smem_u32(smraw);
    float* gate_sm = (float*)(smraw + SM_GATE);

    const int tid  = threadIdx.x;
    const int lane = tid & 31;
    const int wid  = tid >> 5;
    const int wm   = wid & 3;
    const int wn   = wid >> 2;
    const int nBase = blockIdx.x * 64;
    const int mBase = blockIdx.y * 128;
    const int mg    = blockIdx.y;          // m-group
    const int cchunk = blockIdx.x >> 2;    // hidden chunk this CTA produces

    const int lrow_a = ((lane >> 3) & 1) * 8 + (lane & 7);
    const int lrow_b = (lane >> 4) * 8 + (lane & 7);
    const int lxor   = lane & 7;
    const int ahalf  = lane >> 4;
    const int bhalf  = (lane >> 3) & 1;

    // ---- one-time W_hh preload: 16 chunks x 64 rows x 128B, swizzled ----
#pragma unroll
    for (int c = 0; c < 16; c++) {
        const char* Bs = (const char*)(whh + ((size_t)c * 4096 + nBase) * 64);
#pragma unroll
        for (int q = 0; q < 2; q++) {
            const int e = tid + q * 256;
            const int r = e >> 3, s = e & 7;
            const uint32_t off = r * 128 + (((uint32_t)(s ^ (r & 7))) << 4);
            cp_async16(sbase + SM_W + c * 8192u + off, Bs + r * 128 + s * 16);
        }
    }
    cp_commit();

    // per-thread persistent cell state + output weights
    const int bloc = tid >> 1;
    const int b = mBase + bloc;
    const int jh = (tid & 1) * 8;
    const int j0 = (nBase >> 2) + jh;
    float cc[8], wout[8];
#pragma unroll
    for (int jj = 0; jj < 8; jj++) {
        cc[jj]   = c0[b * HH + j0 + jj];
        wout[jj] = W_out[j0 + jj];
    }
    cp_wait<0>();
    __syncthreads();

    for (int t = 0; t < TT; t++) {
        const __half* hcR = (t & 1) ? hc1 : hc0;
        __half*       hcW = (t & 1) ? hc0 : hc1;
        const float*  xg_t = xg + (size_t)t * BB * GG;
        const int target = 4 * t;

        // prefetch this thread's xg slice
        float4 xr[8];
        const float4* xp = (const float4*)(xg_t + (size_t)b * GG + nBase) + jh;
#pragma unroll
        for (int jj = 0; jj < 8; jj++) xr[jj] = xp[jj];

        float c[2][4][4];
#pragma unroll
        for (int i = 0; i < 2; i++)
#pragma unroll
            for (int j = 0; j < 4; j++)
#pragma unroll
                for (int k = 0; k < 4; k++) c[i][j][k] = 0.0f;

        if (t > 0) wait_flag(&g_prog[mg][0], target);
        LOAD_A(hcR, mBase, 0, sbase + SM_A);
        cp_commit();

        for (int i = 0; i < 16; i++) {
            const int buf = i & 1;
            if (i + 1 < 16) {
                if (t > 0) wait_flag(&g_prog[mg][i + 1], target);
                LOAD_A(hcR, mBase, i + 1, sbase + SM_A + ((i + 1) & 1) * 16384u);
                cp_commit();
                cp_wait<1>();
            } else {
                cp_wait<0>();
            }
            __syncthreads();

            const uint32_t aTile = sbase + SM_A + buf * 16384u;
            const uint32_t bTile = sbase + SM_W + i * 8192u;
#pragma unroll
            for (int kk = 0; kk < 4; kk++) {
                uint32_t a[2][4], bfrag[4][2];
#pragma unroll
                for (int mt = 0; mt < 2; mt++) {
                    const int row = wm * 32 + mt * 16 + lrow_a;
                    const uint32_t addr = aTile + row * 128 +
                        (((uint32_t)((kk * 2 + ahalf) ^ lxor)) << 4);
                    ldsm_x4(a[mt][0], a[mt][1], a[mt][2], a[mt][3], addr);
                }
#pragma unroll
                for (int bt = 0; bt < 2; bt++) {
                    const int row = wn * 32 + bt * 16 + lrow_b;
                    const uint32_t addr = bTile + row * 128 +
                        (((uint32_t)((kk * 2 + bhalf) ^ lxor)) << 4);
                    uint32_t r0, r1, r2, r3;
                    ldsm_x4(r0, r1, r2, r3, addr);
                    bfrag[2 * bt][0] = r0;     bfrag[2 * bt][1] = r1;
                    bfrag[2 * bt + 1][0] = r2; bfrag[2 * bt + 1][1] = r3;
                }
#pragma unroll
                for (int mt = 0; mt < 2; mt++)
#pragma unroll
                    for (int nt = 0; nt < 4; nt++)
                        mma16816(c[mt][nt], a[mt], bfrag[nt]);
            }
            __syncthreads();
        }

        // stage MMA result into smem
        const int g  = lane >> 2;
        const int tg = lane & 3;
#pragma unroll
        for (int mt = 0; mt < 2; mt++) {
#pragma unroll
            for (int nt = 0; nt < 4; nt++) {
                const int col = wn * 32 + nt * 8 + tg * 2;
#pragma unroll
                for (int half = 0; half < 2; half++) {
                    const int row = wm * 32 + mt * 16 + g + half * 8;
                    gate_sm[row * GATE_W + col]     = c[mt][nt][half * 2 + 0];
                    gate_sm[row * GATE_W + col + 1] = c[mt][nt][half * 2 + 1];
                }
            }
        }
        __syncthreads();

        // cell math (c in registers across steps)
        float osum = 0.0f;
#pragma unroll
        for (int jj = 0; jj < 8; jj++) {
            const int jloc = jh + jj;
            const int j = (nBase >> 2) + jloc;
            const float4 mm = *(const float4*)&gate_sm[bloc * GATE_W + jloc * 4];
            const float ig = sigf(mm.x + xr[jj].x);
            const float fg = sigf(mm.y + xr[jj].y);
            const float gg = tanhf(mm.z + xr[jj].z);
            const float og = sigf(mm.w + xr[jj].w);
            cc[jj] = fg * cc[jj] + ig * gg;
            const float h = og * tanhf(cc[jj]);

            const int chunk = j >> 6, col = j & 63;
            hcW[((size_t)chunk * BB + b) * 64 + col] = __float2half_rn(h);
            osum += h * wout[jj];
            if (t == TT - 1) { hT[b * HH + j] = h; cT[b * HH + j] = cc[jj]; }
        }
        atomicAdd(&out[t * BB + b], osum);

        // publish our h chunk (release)
        __threadfence();
        __syncthreads();
        if (tid == 0) atomicAdd(&g_prog[mg][cchunk], 1);
    }
}

// ===================== conversion / pointwise kernels ========================
__global__ void split_hi_k(const float* __restrict__ src, __half* __restrict__ dst,
                           int R, int K)
{
    const size_t i = (size_t)blockIdx.x * blockDim.x + threadIdx.x;
    const int r = (int)(i / K);
    const int k = (int)(i - (size_t)r * K);
    const int chunk = k >> 6, col = k & 63;
    dst[((size_t)chunk * R + r) * 64 + col] = __float2half_rn(src[i]);
}

__global__ void split_perm_hi_k(const float* __restrict__ src, __half* __restrict__ dst)
{
    const size_t i = (size_t)blockIdx.x * blockDim.x + threadIdx.x;
    const int r = (int)(i >> 10);
    const int k = (int)(i & 1023);
    const int gt = r >> 10, j = r & 1023;
    const int rp = j * 4 + gt;
    const int chunk = k >> 6, col = k & 63;
    dst[((size_t)chunk * 4096 + rp) * 64 + col] = __float2half_rn(src[i]);
}

// merged setup: bias combine + h0 convert + out init + flag reset
__global__ void setup_k(const float* __restrict__ b_ih, const float* __restrict__ b_hh,
                        const float* __restrict__ h0,
                        float* __restrict__ out, const float* __restrict__ b_out)
{
    const int i = blockIdx.x * blockDim.x + threadIdx.x;  // [0, B*H)
    if (i < 32) ((int*)g_prog)[i] = 0;
    if (i < GG) {
        const int gt = i & 3, j = i >> 2;
        const int s = gt * HH + j;
        g_bias[i] = b_ih[s] + b_hh[s];
    }
    if (i < TT * BB) out[i] = b_out[0];
    const int b = i >> 10, j = i & 1023;
    const int chunk = j >> 6, col = j & 63;
    g_hc[((size_t)chunk * BB + b) * 64 + col] = __float2half_rn(h0[i]);
}

// ===================== launch ================================================
#define SMEM_BIG 65536

extern "C" void kernel_launch(void* const* d_in, const int* in_sizes, int n_in,
                              void* d_out, int out_size)
{
    const float* inputs = (const float*)d_in[0];
    const float* h0     = (const float*)d_in[1];
    const float* c0     = (const float*)d_in[2];
    const float* W1     = (const float*)d_in[3];
    const float* b1     = (const float*)d_in[4];
    const float* W_ih   = (const float*)d_in[5];
    const float* W_hh   = (const float*)d_in[6];
    const float* b_ih   = (const float*)d_in[7];
    const float* b_hh   = (const float*)d_in[8];
    const float* W_out  = (const float*)d_in[9];
    const float* b_out  = (const float*)d_in[10];

    float* out = (float*)d_out;
    float* hT  = out + TT * BB;
    float* cT  = hT + BB * HH;

    __half *pinc, *pxc, *pw1c, *pwihc, *pwhhc, *phc;
    float *pxg, *pbias;
    cudaGetSymbolAddress((void**)&pinc,  g_inc);
    cudaGetSymbolAddress((void**)&pxc,   g_xc);
    cudaGetSymbolAddress((void**)&pw1c,  g_w1c);
    cudaGetSymbolAddress((void**)&pwihc, g_wihc);
    cudaGetSymbolAddress((void**)&pwhhc, g_whhc);
    cudaGetSymbolAddress((void**)&phc,   g_hc);
    cudaGetSymbolAddress((void**)&pxg,   g_xg);
    cudaGetSymbolAddress((void**)&pbias, g_bias);

    cudaFuncSetAttribute((const void*)gemm_mma<0>, cudaFuncAttributeMaxDynamicSharedMemorySize, SMEM_BIG);
    cudaFuncSetAttribute((const void*)gemm_mma<1>, cudaFuncAttributeMaxDynamicSharedMemorySize, SMEM_BIG);
    cudaFuncSetAttribute((const void*)rec_persist_k, cudaFuncAttributeMaxDynamicSharedMemorySize, SMEM_REC);

    // conversions (all hi-only)
    split_hi_k<<<(32768 * 512) / 256, 256>>>(inputs, pinc, 32768, 512);
    split_hi_k<<<(1024 * 512) / 256, 256>>>(W1, pw1c, 1024, 512);
    split_perm_hi_k<<<(4096 * 1024) / 256, 256>>>(W_ih, pwihc);
    split_perm_hi_k<<<(4096 * 1024) / 256, 256>>>(W_hh, pwhhc);
    setup_k<<<(BB * HH) / 256, 256>>>(b_ih, b_hh, h0, out, b_out);

    // GEMM1: x = relu(inputs @ W1^T + b1) -> hi store g_xc  (1-pass, C=8)
    {
        dim3 grid(HH / 128, 32768 / 128);
        gemm_mma<0><<<grid, 256, SMEM_BIG>>>(pinc, pw1c, b1, nullptr, pxc, 32768, HH, 8);
    }
    // GEMM2: xg' = x_hi @ W_ih_hi'^T + bias' -> g_xg  (1-pass, C=16)
    {
        dim3 grid(GG / 128, 32768 / 128);
        gemm_mma<1><<<grid, 256, SMEM_BIG>>>(pxc, pwihc, pbias, pxg, nullptr, 32768, GG, 16);
    }
    // persistent recurrence: single launch, 128 co-resident CTAs, flag-pipelined
    {
        dim3 grid(GG / 64, BB / 128);
        rec_persist_k<<<grid, 256, SMEM_REC>>>(phc, phc + HSPLIT, pwhhc, pxg,
                                               W_out, c0, out, hT, cT);
    }
}

// round 12
// speedup vs baseline: 1.3978x; 1.3978x over previous
#include <cuda_runtime.h>
#include <cuda_fp16.h>
#include <math.h>
#include <stdint.h>

#define TT 128
#define BB 256
#define DD 512
#define HH 1024
#define GG 4096   // 4*H

// ===================== scratch (static device globals) ======================
__device__ __align__(16) __half g_inc [(size_t)8  * 32768 * 64]; // inputs hi (C=8)
__device__ __align__(16) __half g_xc  [(size_t)16 * 32768 * 64]; // x hi      (C=16)
__device__ __align__(16) __half g_w1c [(size_t)8  * 1024  * 64]; // W1 hi
__device__ __align__(16) __half g_wihc[(size_t)16 * 4096  * 64]; // W_ih hi (gate-perm)
__device__ __align__(16) __half g_whhc[(size_t)16 * 4096  * 64]; // W_hh hi (gate-perm)
#define HSPLIT ((size_t)16 * 256 * 64)
__device__ __align__(16) __half g_hc  [2 * HSPLIT];              // h hi, ping-pong
__device__ __align__(16) float g_xg[(size_t)TT * BB * GG];       // gate-perm cols
__device__ __align__(16) float g_bias[GG];                       // gate-perm
__device__ int g_bar;                                            // global step barrier

// ===================== PTX helpers ==========================================
__device__ __forceinline__ uint32_t smem_u32(const void* p) {
    return (uint32_t)__cvta_generic_to_shared(p);
}
__device__ __forceinline__ void cp_async16(uint32_t dst, const void* src) {
    asm volatile("cp.async.cg.shared.global [%0], [%1], 16;" :: "r"(dst), "l"(src));
}
__device__ __forceinline__ void cp_commit() {
    asm volatile("cp.async.commit_group;" ::: "memory");
}
template<int N>
__device__ __forceinline__ void cp_wait() {
    asm volatile("cp.async.wait_group %0;" :: "n"(N) : "memory");
}
__device__ __forceinline__ void ldsm_x4(uint32_t& r0, uint32_t& r1, uint32_t& r2, uint32_t& r3,
                                        uint32_t addr) {
    asm volatile("ldmatrix.sync.aligned.m8n8.x4.shared.b16 {%0,%1,%2,%3}, [%4];"
                 : "=r"(r0), "=r"(r1), "=r"(r2), "=r"(r3) : "r"(addr));
}
__device__ __forceinline__ void mma16816(float* c, const uint32_t* a, const uint32_t* b) {
    asm volatile(
        "mma.sync.aligned.m16n8k16.row.col.f32.f16.f16.f32 "
        "{%0,%1,%2,%3}, {%4,%5,%6,%7}, {%8,%9}, {%0,%1,%2,%3};"
        : "+f"(c[0]), "+f"(c[1]), "+f"(c[2]), "+f"(c[3])
        : "r"(a[0]), "r"(a[1]), "r"(a[2]), "r"(a[3]), "r"(b[0]), "r"(b[1]));
}

__device__ __forceinline__ void store_hi(__half* dst, int M, int m, int n, float v) {
    const int chunk = n >> 6, col = n & 63;
    dst[((size_t)chunk * M + m) * 64 + col] = __float2half_rn(v);
}

// chunk loader: A tile RA rows, B tile RB rows, 128B rows, XOR-swizzled
#define LOAD_CHUNK(A_, B_, M_, N_, mB_, nB_, RA_, RB_, ac_, bc_, dA_)             \
    do {                                                                          \
        const char* As_ = (const char*)((A_) + ((size_t)(ac_) * (M_) + (mB_)) * 64);\
        const char* Bs_ = (const char*)((B_) + ((size_t)(bc_) * (N_) + (nB_)) * 64);\
        const uint32_t dB_ = (dA_) + (RA_) * 128u;                                \
        _Pragma("unroll")                                                         \
        for (int q_ = 0; q_ < (RA_) / 32; q_++) {                                 \
            const int e_ = tid + q_ * 256;                                        \
            const int r_ = e_ >> 3, s_ = e_ & 7;                                  \
            const uint32_t off_ = r_ * 128 + (((uint32_t)(s_ ^ (r_ & 7))) << 4);  \
            cp_async16((dA_) + off_, As_ + r_ * 128 + s_ * 16);                   \
        }                                                                         \
        _Pragma("unroll")                                                         \
        for (int q_ = 0; q_ < (RB_) / 32; q_++) {                                 \
            const int e_ = tid + q_ * 256;                                        \
            const int r_ = e_ >> 3, s_ = e_ & 7;                                  \
            const uint32_t off_ = r_ * 128 + (((uint32_t)(s_ ^ (r_ & 7))) << 4);  \
            cp_async16(dB_ + off_, Bs_ + r_ * 128 + s_ * 16);                     \
        }                                                                         \
    } while (0)

// A-only loader (128 rows)
#define LOAD_A(A_, mB_, ac_, dA_)                                                 \
    do {                                                                          \
        const char* As_ = (const char*)((A_) + ((size_t)(ac_) * 256 + (mB_)) * 64);\
        _Pragma("unroll")                                                         \
        for (int q_ = 0; q_ < 4; q_++) {                                          \
            const int e_ = tid + q_ * 256;                                        \
            const int r_ = e_ >> 3, s_ = e_ & 7;                                  \
            const uint32_t off_ = r_ * 128 + (((uint32_t)(s_ ^ (r_ & 7))) << 4);  \
            cp_async16((dA_) + off_, As_ + r_ * 128 + s_ * 16);                   \
        }                                                                         \
    } while (0)

// ===================== big GEMMs (BM=BN=128, 1-pass fp16, 2 CTA/SM) ==========
// MODE 0: v=relu(v+aux[n]) -> hi store; MODE 1: v=v+aux[n] -> outF
template<int MODE>
__global__ __launch_bounds__(256, 2)
void gemm_mma(const __half* __restrict__ A, const __half* __restrict__ B,
              const float* __restrict__ aux, float* __restrict__ outF,
              __half* __restrict__ outSplit, int M, int N, int C)
{
    extern __shared__ char smraw[];
    const uint32_t sbase = smem_u32(smraw);

    const int tid  = threadIdx.x;
    const int lane = tid & 31;
    const int wid  = tid >> 5;
    const int wm   = wid & 3;
    const int wn   = wid >> 2;
    const int mBase = blockIdx.y * 128;
    const int nBase = blockIdx.x * 128;
    const int NIT = C;

    float c[2][8][4];
#pragma unroll
    for (int i = 0; i < 2; i++)
#pragma unroll
        for (int j = 0; j < 8; j++)
#pragma unroll
            for (int k = 0; k < 4; k++) c[i][j][k] = 0.0f;

    const int lrow_a = ((lane >> 3) & 1) * 8 + (lane & 7);
    const int lrow_b = (lane >> 4) * 8 + (lane & 7);
    const int lxor   = lane & 7;
    const int ahalf  = lane >> 4;
    const int bhalf  = (lane >> 3) & 1;

    LOAD_CHUNK(A, B, M, N, mBase, nBase, 128, 128, 0, 0, sbase);
    cp_commit();

    for (int i = 0; i < NIT; i++) {
        const int buf = i & 1;
        if (i + 1 < NIT) {
            LOAD_CHUNK(A, B, M, N, mBase, nBase, 128, 128, i + 1, i + 1,
                       sbase + ((i + 1) & 1) * 32768u);
            cp_commit();
            cp_wait<1>();
        } else {
            cp_wait<0>();
        }
        __syncthreads();

        const uint32_t aTile = sbase + buf * 32768u;
        const uint32_t bTile = aTile + 16384u;
#pragma unroll
        for (int kk = 0; kk < 4; kk++) {
            uint32_t a[2][4], b[8][2];
#pragma unroll
            for (int mt = 0; mt < 2; mt++) {
                const int row = wm * 32 + mt * 16 + lrow_a;
                const uint32_t addr = aTile + row * 128 +
                    (((uint32_t)((kk * 2 + ahalf) ^ lxor)) << 4);
                ldsm_x4(a[mt][0], a[mt][1], a[mt][2], a[mt][3], addr);
            }
#pragma unroll
            for (int bt = 0; bt < 4; bt++) {
                const int row = wn * 64 + bt * 16 + lrow_b;
                const uint32_t addr = bTile + row * 128 +
                    (((uint32_t)((kk * 2 + bhalf) ^ lxor)) << 4);
                uint32_t r0, r1, r2, r3;
                ldsm_x4(r0, r1, r2, r3, addr);
                b[2 * bt][0] = r0;     b[2 * bt][1] = r1;
                b[2 * bt + 1][0] = r2; b[2 * bt + 1][1] = r3;
            }
#pragma unroll
            for (int mt = 0; mt < 2; mt++)
#pragma unroll
                for (int nt = 0; nt < 8; nt++)
                    mma16816(c[mt][nt], a[mt], b[nt]);
        }
        __syncthreads();
    }

    const int g  = lane >> 2;
    const int tg = lane & 3;
#pragma unroll
    for (int mt = 0; mt < 2; mt++) {
        const int m0 = mBase + wm * 32 + mt * 16 + g;
#pragma unroll
        for (int nt = 0; nt < 8; nt++) {
            const int n0 = nBase + wn * 64 + nt * 8 + tg * 2;
#pragma unroll
            for (int half = 0; half < 2; half++) {
                const int m = m0 + half * 8;
                const float v0 = c[mt][nt][half * 2 + 0];
                const float v1 = c[mt][nt][half * 2 + 1];
                if (MODE == 0) {
                    store_hi(outSplit, M, m, n0,     fmaxf(v0 + aux[n0],     0.0f));
                    store_hi(outSplit, M, m, n0 + 1, fmaxf(v1 + aux[n0 + 1], 0.0f));
                } else {
                    float2 r = make_float2(v0 + aux[n0], v1 + aux[n0 + 1]);
                    *(float2*)(outF + (size_t)m * N + n0) = r;
                }
            }
        }
    }
}

// ===================== persistent fused recurrence ===========================
// W_hh resident in smem; single global barrier per step (tid-0 spin only).
// smem layout: [0,128K) W chunks | [128K,160K) A dbl-buf | [160K,+34.8K) gates
#define GATE_W 68
#define NCTAS 128
#define SM_W    0u
#define SM_A    131072u
#define SM_GATE 163840u
#define SMEM_REC (163840 + 128 * GATE_W * 4)

__device__ __forceinline__ float sigf(float x) { return 1.0f / (1.0f + __expf(-x)); }

__global__ __launch_bounds__(256, 1)
void rec_persist_k(__half* __restrict__ hc0, __half* __restrict__ hc1,
                   const __half* __restrict__ whh, const float* __restrict__ xg,
                   const float* __restrict__ W_out, const float* __restrict__ c0,
                   float* __restrict__ out, float* __restrict__ hT, float* __restrict__ cT)
{
    extern __shared__ char smraw[];
    const uint32_t sbase = smem_u32(smraw);
    float* gate_sm = (float*)(smraw + SM_GATE);

    const int tid  = threadIdx.x;
    const int lane = tid & 31;
    const int wid  = tid >> 5;
    const int wm   = wid & 3;
    const int wn   = wid >> 2;
    const int nBase = blockIdx.x * 64;
    const int mBase = blockIdx.y * 128;

    const int lrow_a = ((lane >> 3) & 1) * 8 + (lane & 7);
    const int lrow_b = (lane >> 4) * 8 + (lane & 7);
    const int lxor   = lane & 7;
    const int ahalf  = lane >> 4;
    const int bhalf  = (lane >> 3) & 1;

    // ---- one-time W_hh preload: 16 chunks x 64 rows x 128B, swizzled ----
#pragma unroll
    for (int c = 0; c < 16; c++) {
        const char* Bs = (const char*)(whh + ((size_t)c * 4096 + nBase) * 64);
#pragma unroll
        for (int q = 0; q < 2; q++) {
            const int e = tid + q * 256;
            const int r = e >> 3, s = e & 7;
            const uint32_t off = r * 128 + (((uint32_t)(s ^ (r & 7))) << 4);
            cp_async16(sbase + SM_W + c * 8192u + off, Bs + r * 128 + s * 16);
        }
    }
    cp_commit();

    // per-thread persistent cell state + output weights
    const int bloc = tid >> 1;
    const int b = mBase + bloc;
    const int jh = (tid & 1) * 8;
    const int j0 = (nBase >> 2) + jh;
    float cc[8], wout[8];
#pragma unroll
    for (int jj = 0; jj < 8; jj++) {
        cc[jj]   = c0[b * HH + j0 + jj];
        wout[jj] = W_out[j0 + jj];
    }

    volatile int* barp = &g_bar;
    cp_wait<0>();
    __syncthreads();

    for (int t = 0; t < TT; t++) {
        const __half* hcR = (t & 1) ? hc1 : hc0;
        __half*       hcW = (t & 1) ? hc0 : hc1;
        const float*  xg_t = xg + (size_t)t * BB * GG;

        // prefetch this thread's xg slice
        float4 xr[8];
        const float4* xp = (const float4*)(xg_t + (size_t)b * GG + nBase) + jh;
#pragma unroll
        for (int jj = 0; jj < 8; jj++) xr[jj] = xp[jj];

        float c[2][4][4];
#pragma unroll
        for (int i = 0; i < 2; i++)
#pragma unroll
            for (int j = 0; j < 4; j++)
#pragma unroll
                for (int k = 0; k < 4; k++) c[i][j][k] = 0.0f;

        LOAD_A(hcR, mBase, 0, sbase + SM_A);
        cp_commit();

        for (int i = 0; i < 16; i++) {
            const int buf = i & 1;
            if (i + 1 < 16) {
                LOAD_A(hcR, mBase, i + 1, sbase + SM_A + ((i + 1) & 1) * 16384u);
                cp_commit();
                cp_wait<1>();
            } else {
                cp_wait<0>();
            }
            __syncthreads();

            const uint32_t aTile = sbase + SM_A + buf * 16384u;
            const uint32_t bTile = sbase + SM_W + i * 8192u;
#pragma unroll
            for (int kk = 0; kk < 4; kk++) {
                uint32_t a[2][4], bfrag[4][2];
#pragma unroll
                for (int mt = 0; mt < 2; mt++) {
                    const int row = wm * 32 + mt * 16 + lrow_a;
                    const uint32_t addr = aTile + row * 128 +
                        (((uint32_t)((kk * 2 + ahalf) ^ lxor)) << 4);
                    ldsm_x4(a[mt][0], a[mt][1], a[mt][2], a[mt][3], addr);
                }
#pragma unroll
                for (int bt = 0; bt < 2; bt++) {
                    const int row = wn * 32 + bt * 16 + lrow_b;
                    const uint32_t addr = bTile + row * 128 +
                        (((uint32_t)((kk * 2 + bhalf) ^ lxor)) << 4);
                    uint32_t r0, r1, r2, r3;
                    ldsm_x4(r0, r1, r2, r3, addr);
                    bfrag[2 * bt][0] = r0;     bfrag[2 * bt][1] = r1;
                    bfrag[2 * bt + 1][0] = r2; bfrag[2 * bt + 1][1] = r3;
                }
#pragma unroll
                for (int mt = 0; mt < 2; mt++)
#pragma unroll
                    for (int nt = 0; nt < 4; nt++)
                        mma16816(c[mt][nt], a[mt], bfrag[nt]);
            }
            __syncthreads();
        }

        // stage MMA result into smem
        const int g  = lane >> 2;
        const int tg = lane & 3;
#pragma unroll
        for (int mt = 0; mt < 2; mt++) {
#pragma unroll
            for (int nt = 0; nt < 4; nt++) {
                const int col = wn * 32 + nt * 8 + tg * 2;
#pragma unroll
                for (int half = 0; half < 2; half++) {
                    const int row = wm * 32 + mt * 16 + g + half * 8;
                    gate_sm[row * GATE_W + col]     = c[mt][nt][half * 2 + 0];
                    gate_sm[row * GATE_W + col + 1] = c[mt][nt][half * 2 + 1];
                }
            }
        }
        __syncthreads();

        // cell math (c in registers across steps)
        float osum = 0.0f;
#pragma unroll
        for (int jj = 0; jj < 8; jj++) {
            const int jloc = jh + jj;
            const int j = (nBase >> 2) + jloc;
            const float4 mm = *(const float4*)&gate_sm[bloc * GATE_W + jloc * 4];
            const float ig = sigf(mm.x + xr[jj].x);
            const float fg = sigf(mm.y + xr[jj].y);
            const float gg = tanhf(mm.z + xr[jj].z);
            const float og = sigf(mm.w + xr[jj].w);
            cc[jj] = fg * cc[jj] + ig * gg;
            const float h = og * tanhf(cc[jj]);

            const int chunk = j >> 6, col = j & 63;
            hcW[((size_t)chunk * BB + b) * 64 + col] = __float2half_rn(h);
            osum += h * wout[jj];
            if (t == TT - 1) { hT[b * HH + j] = h; cT[b * HH + j] = cc[jj]; }
        }
        atomicAdd(&out[t * BB + b], osum);

        // global step barrier (tid-0 spin only)
        __threadfence();
        __syncthreads();
        if (tid == 0) {
            atomicAdd(&g_bar, 1);
            const int target = NCTAS * (t + 1);
            while (*barp < target) { __nanosleep(64); }
        }
        __syncthreads();
        __threadfence();
    }
}

// ===================== conversion / pointwise kernels ========================
__global__ void split_hi_k(const float* __restrict__ src, __half* __restrict__ dst,
                           int R, int K)
{
    const size_t i = (size_t)blockIdx.x * blockDim.x + threadIdx.x;
    const int r = (int)(i / K);
    const int k = (int)(i - (size_t)r * K);
    const int chunk = k >> 6, col = k & 63;
    dst[((size_t)chunk * R + r) * 64 + col] = __float2half_rn(src[i]);
}

__global__ void split_perm_hi_k(const float* __restrict__ src, __half* __restrict__ dst)
{
    const size_t i = (size_t)blockIdx.x * blockDim.x + threadIdx.x;
    const int r = (int)(i >> 10);
    const int k = (int)(i & 1023);
    const int gt = r >> 10, j = r & 1023;
    const int rp = j * 4 + gt;
    const int chunk = k >> 6, col = k & 63;
    dst[((size_t)chunk * 4096 + rp) * 64 + col] = __float2half_rn(src[i]);
}

// merged setup: bias combine + h0 convert + out init + barrier reset
__global__ void setup_k(const float* __restrict__ b_ih, const float* __restrict__ b_hh,
                        const float* __restrict__ h0,
                        float* __restrict__ out, const float* __restrict__ b_out)
{
    const int i = blockIdx.x * blockDim.x + threadIdx.x;  // [0, B*H)
    if (i == 0) g_bar = 0;
    if (i < GG) {
        const int gt = i & 3, j = i >> 2;
        const int s = gt * HH + j;
        g_bias[i] = b_ih[s] + b_hh[s];
    }
    if (i < TT * BB) out[i] = b_out[0];
    const int b = i >> 10, j = i & 1023;
    const int chunk = j >> 6, col = j & 63;
    g_hc[((size_t)chunk * BB + b) * 64 + col] = __float2half_rn(h0[i]);
}

// ===================== launch ================================================
#define SMEM_BIG 65536

extern "C" void kernel_launch(void* const* d_in, const int* in_sizes, int n_in,
                              void* d_out, int out_size)
{
    const float* inputs = (const float*)d_in[0];
    const float* h0     = (const float*)d_in[1];
    const float* c0     = (const float*)d_in[2];
    const float* W1     = (const float*)d_in[3];
    const float* b1     = (const float*)d_in[4];
    const float* W_ih   = (const float*)d_in[5];
    const float* W_hh   = (const float*)d_in[6];
    const float* b_ih   = (const float*)d_in[7];
    const float* b_hh   = (const float*)d_in[8];
    const float* W_out  = (const float*)d_in[9];
    const float* b_out  = (const float*)d_in[10];

    float* out = (float*)d_out;
    float* hT  = out + TT * BB;
    float* cT  = hT + BB * HH;

    __half *pinc, *pxc, *pw1c, *pwihc, *pwhhc, *phc;
    float *pxg, *pbias;
    cudaGetSymbolAddress((void**)&pinc,  g_inc);
    cudaGetSymbolAddress((void**)&pxc,   g_xc);
    cudaGetSymbolAddress((void**)&pw1c,  g_w1c);
    cudaGetSymbolAddress((void**)&pwihc, g_wihc);
    cudaGetSymbolAddress((void**)&pwhhc, g_whhc);
    cudaGetSymbolAddress((void**)&phc,   g_hc);
    cudaGetSymbolAddress((void**)&pxg,   g_xg);
    cudaGetSymbolAddress((void**)&pbias, g_bias);

    cudaFuncSetAttribute((const void*)gemm_mma<0>, cudaFuncAttributeMaxDynamicSharedMemorySize, SMEM_BIG);
    cudaFuncSetAttribute((const void*)gemm_mma<1>, cudaFuncAttributeMaxDynamicSharedMemorySize, SMEM_BIG);
    cudaFuncSetAttribute((const void*)rec_persist_k, cudaFuncAttributeMaxDynamicSharedMemorySize, SMEM_REC);

    // conversions (all hi-only)
    split_hi_k<<<(32768 * 512) / 256, 256>>>(inputs, pinc, 32768, 512);
    split_hi_k<<<(1024 * 512) / 256, 256>>>(W1, pw1c, 1024, 512);
    split_perm_hi_k<<<(4096 * 1024) / 256, 256>>>(W_ih, pwihc);
    split_perm_hi_k<<<(4096 * 1024) / 256, 256>>>(W_hh, pwhhc);
    setup_k<<<(BB * HH) / 256, 256>>>(b_ih, b_hh, h0, out, b_out);

    // GEMM1: x = relu(inputs @ W1^T + b1) -> hi store g_xc  (1-pass, C=8)
    {
        dim3 grid(HH / 128, 32768 / 128);
        gemm_mma<0><<<grid, 256, SMEM_BIG>>>(pinc, pw1c, b1, nullptr, pxc, 32768, HH, 8);
    }
    // GEMM2: xg' = x_hi @ W_ih_hi'^T + bias' -> g_xg  (1-pass, C=16)
    {
        dim3 grid(GG / 128, 32768 / 128);
        gemm_mma<1><<<grid, 256, SMEM_BIG>>>(pxc, pwihc, pbias, pxg, nullptr, 32768, GG, 16);
    }
    // persistent recurrence: single launch, 128 co-resident CTAs, smem-resident W
    {
        dim3 grid(GG / 64, BB / 128);
        rec_persist_k<<<grid, 256, SMEM_REC>>>(phc, phc + HSPLIT, pwhhc, pxg,
                                               W_out, c0, out, hT, cT);
    }
}

// round 13
// speedup vs baseline: 1.4348x; 1.0265x over previous
#include <cuda_runtime.h>
#include <cuda_fp16.h>
#include <math.h>
#include <stdint.h>

#define TT 128
#define BB 256
#define DD 512
#define HH 1024
#define GG 4096   // 4*H

// ===================== scratch (static device globals) ======================
__device__ __align__(16) __half g_inc [(size_t)8  * 32768 * 64]; // inputs hi (C=8)
__device__ __align__(16) __half g_xc  [(size_t)16 * 32768 * 64]; // x hi      (C=16)
__device__ __align__(16) __half g_w1c [(size_t)8  * 1024  * 64]; // W1 hi
__device__ __align__(16) __half g_wihc[(size_t)16 * 4096  * 64]; // W_ih hi (gate-perm)
__device__ __align__(16) __half g_whhc[(size_t)16 * 4096  * 64]; // W_hh hi (gate-perm)
#define HSPLIT ((size_t)16 * 256 * 64)
__device__ __align__(16) __half g_hc  [2 * HSPLIT];              // h hi, ping-pong
__device__ __align__(16) float g_xg[(size_t)TT * BB * GG];       // gate-perm cols
__device__ __align__(16) float g_bias[GG];                       // gate-perm
__device__ int g_bar[2];                                         // per-m-group step barrier

// ===================== PTX helpers ==========================================
__device__ __forceinline__ uint32_t smem_u32(const void* p) {
    return (uint32_t)__cvta_generic_to_shared(p);
}
__device__ __forceinline__ void cp_async16(uint32_t dst, const void* src) {
    asm volatile("cp.async.cg.shared.global [%0], [%1], 16;" :: "r"(dst), "l"(src));
}
__device__ __forceinline__ void cp_commit() {
    asm volatile("cp.async.commit_group;" ::: "memory");
}
template<int N>
__device__ __forceinline__ void cp_wait() {
    asm volatile("cp.async.wait_group %0;" :: "n"(N) : "memory");
}
__device__ __forceinline__ void ldsm_x4(uint32_t& r0, uint32_t& r1, uint32_t& r2, uint32_t& r3,
                                        uint32_t addr) {
    asm volatile("ldmatrix.sync.aligned.m8n8.x4.shared.b16 {%0,%1,%2,%3}, [%4];"
                 : "=r"(r0), "=r"(r1), "=r"(r2), "=r"(r3) : "r"(addr));
}
__device__ __forceinline__ void mma16816(float* c, const uint32_t* a, const uint32_t* b) {
    asm volatile(
        "mma.sync.aligned.m16n8k16.row.col.f32.f16.f16.f32 "
        "{%0,%1,%2,%3}, {%4,%5,%6,%7}, {%8,%9}, {%0,%1,%2,%3};"
        : "+f"(c[0]), "+f"(c[1]), "+f"(c[2]), "+f"(c[3])
        : "r"(a[0]), "r"(a[1]), "r"(a[2]), "r"(a[3]), "r"(b[0]), "r"(b[1]));
}

__device__ __forceinline__ void store_hi(__half* dst, int M, int m, int n, float v) {
    const int chunk = n >> 6, col = n & 63;
    dst[((size_t)chunk * M + m) * 64 + col] = __float2half_rn(v);
}

// chunk loader: A tile RA rows, B tile RB rows, 128B rows, XOR-swizzled
#define LOAD_CHUNK(A_, B_, M_, N_, mB_, nB_, RA_, RB_, ac_, bc_, dA_)             \
    do {                                                                          \
        const char* As_ = (const char*)((A_) + ((size_t)(ac_) * (M_) + (mB_)) * 64);\
        const char* Bs_ = (const char*)((B_) + ((size_t)(bc_) * (N_) + (nB_)) * 64);\
        const uint32_t dB_ = (dA_) + (RA_) * 128u;                                \
        _Pragma("unroll")                                                         \
        for (int q_ = 0; q_ < (RA_) / 32; q_++) {                                 \
            const int e_ = tid + q_ * 256;                                        \
            const int r_ = e_ >> 3, s_ = e_ & 7;                                  \
            const uint32_t off_ = r_ * 128 + (((uint32_t)(s_ ^ (r_ & 7))) << 4);  \
            cp_async16((dA_) + off_, As_ + r_ * 128 + s_ * 16);                   \
        }                                                                         \
        _Pragma("unroll")                                                         \
        for (int q_ = 0; q_ < (RB_) / 32; q_++) {                                 \
            const int e_ = tid + q_ * 256;                                        \
            const int r_ = e_ >> 3, s_ = e_ & 7;                                  \
            const uint32_t off_ = r_ * 128 + (((uint32_t)(s_ ^ (r_ & 7))) << 4);  \
            cp_async16(dB_ + off_, Bs_ + r_ * 128 + s_ * 16);                     \
        }                                                                         \
    } while (0)

// A-only loader (128 rows)
#define LOAD_A(A_, mB_, ac_, dA_)                                                 \
    do {                                                                          \
        const char* As_ = (const char*)((A_) + ((size_t)(ac_) * 256 + (mB_)) * 64);\
        _Pragma("unroll")                                                         \
        for (int q_ = 0; q_ < 4; q_++) {                                          \
            const int e_ = tid + q_ * 256;                                        \
            const int r_ = e_ >> 3, s_ = e_ & 7;                                  \
            const uint32_t off_ = r_ * 128 + (((uint32_t)(s_ ^ (r_ & 7))) << 4);  \
            cp_async16((dA_) + off_, As_ + r_ * 128 + s_ * 16);                   \
        }                                                                         \
    } while (0)

// ===================== big GEMMs (BM=BN=128, 1-pass fp16, 2 CTA/SM) ==========
// MODE 0: v=relu(v+aux[n]) -> hi store; MODE 1: v=v+aux[n] -> outF
template<int MODE>
__global__ __launch_bounds__(256, 2)
void gemm_mma(const __half* __restrict__ A, const __half* __restrict__ B,
              const float* __restrict__ aux, float* __restrict__ outF,
              __half* __restrict__ outSplit, int M, int N, int C)
{
    extern __shared__ char smraw[];
    const uint32_t sbase = smem_u32(smraw);

    const int tid  = threadIdx.x;
    const int lane = tid & 31;
    const int wid  = tid >> 5;
    const int wm   = wid & 3;
    const int wn   = wid >> 2;
    const int mBase = blockIdx.y * 128;
    const int nBase = blockIdx.x * 128;
    const int NIT = C;

    float c[2][8][4];
#pragma unroll
    for (int i = 0; i < 2; i++)
#pragma unroll
        for (int j = 0; j < 8; j++)
#pragma unroll
            for (int k = 0; k < 4; k++) c[i][j][k] = 0.0f;

    const int lrow_a = ((lane >> 3) & 1) * 8 + (lane & 7);
    const int lrow_b = (lane >> 4) * 8 + (lane & 7);
    const int lxor   = lane & 7;
    const int ahalf  = lane >> 4;
    const int bhalf  = (lane >> 3) & 1;

    LOAD_CHUNK(A, B, M, N, mBase, nBase, 128, 128, 0, 0, sbase);
    cp_commit();

    for (int i = 0; i < NIT; i++) {
        const int buf = i & 1;
        if (i + 1 < NIT) {
            LOAD_CHUNK(A, B, M, N, mBase, nBase, 128, 128, i + 1, i + 1,
                       sbase + ((i + 1) & 1) * 32768u);
            cp_commit();
            cp_wait<1>();
        } else {
            cp_wait<0>();
        }
        __syncthreads();

        const uint32_t aTile = sbase + buf * 32768u;
        const uint32_t bTile = aTile + 16384u;
#pragma unroll
        for (int kk = 0; kk < 4; kk++) {
            uint32_t a[2][4], b[8][2];
#pragma unroll
            for (int mt = 0; mt < 2; mt++) {
                const int row = wm * 32 + mt * 16 + lrow_a;
                const uint32_t addr = aTile + row * 128 +
                    (((uint32_t)((kk * 2 + ahalf) ^ lxor)) << 4);
                ldsm_x4(a[mt][0], a[mt][1], a[mt][2], a[mt][3], addr);
            }
#pragma unroll
            for (int bt = 0; bt < 4; bt++) {
                const int row = wn * 64 + bt * 16 + lrow_b;
                const uint32_t addr = bTile + row * 128 +
                    (((uint32_t)((kk * 2 + bhalf) ^ lxor)) << 4);
                uint32_t r0, r1, r2, r3;
                ldsm_x4(r0, r1, r2, r3, addr);
                b[2 * bt][0] = r0;     b[2 * bt][1] = r1;
                b[2 * bt + 1][0] = r2; b[2 * bt + 1][1] = r3;
            }
#pragma unroll
            for (int mt = 0; mt < 2; mt++)
#pragma unroll
                for (int nt = 0; nt < 8; nt++)
                    mma16816(c[mt][nt], a[mt], b[nt]);
        }
        __syncthreads();
    }

    const int g  = lane >> 2;
    const int tg = lane & 3;
#pragma unroll
    for (int mt = 0; mt < 2; mt++) {
        const int m0 = mBase + wm * 32 + mt * 16 + g;
#pragma unroll
        for (int nt = 0; nt < 8; nt++) {
            const int n0 = nBase + wn * 64 + nt * 8 + tg * 2;
#pragma unroll
            for (int half = 0; half < 2; half++) {
                const int m = m0 + half * 8;
                const float v0 = c[mt][nt][half * 2 + 0];
                const float v1 = c[mt][nt][half * 2 + 1];
                if (MODE == 0) {
                    store_hi(outSplit, M, m, n0,     fmaxf(v0 + aux[n0],     0.0f));
                    store_hi(outSplit, M, m, n0 + 1, fmaxf(v1 + aux[n0 + 1], 0.0f));
                } else {
                    float2 r = make_float2(v0 + aux[n0], v1 + aux[n0 + 1]);
                    *(float2*)(outF + (size_t)m * N + n0) = r;
                }
            }
        }
    }
}

// ===================== persistent fused recurrence ===========================
// W_hh resident in smem; 4-deep A pipeline, ONE syncthreads/iter;
// per-m-group barrier (64 arrivals).
// smem: [0,128K) W | [128K,192K) A x4 | [192K,+34.8K) gates  -> 231424 B
#define GATE_W 68
#define SM_W    0u
#define SM_A    131072u
#define SM_GATE 196608u
#define SMEM_REC (196608 + 128 * GATE_W * 4)

__device__ __forceinline__ float sigf(float x) { return 1.0f / (1.0f + __expf(-x)); }

__global__ __launch_bounds__(256, 1)
void rec_persist_k(__half* __restrict__ hc0, __half* __restrict__ hc1,
                   const __half* __restrict__ whh, const float* __restrict__ xg,
                   const float* __restrict__ W_out, const float* __restrict__ c0,
                   float* __restrict__ out, float* __restrict__ hT, float* __restrict__ cT)
{
    extern __shared__ char smraw[];
    const uint32_t sbase = smem_u32(smraw);
    float* gate_sm = (float*)(smraw + SM_GATE);

    const int tid  = threadIdx.x;
    const int lane = tid & 31;
    const int wid  = tid >> 5;
    const int wm   = wid & 3;
    const int wn   = wid >> 2;
    const int nBase = blockIdx.x * 64;
    const int mBase = blockIdx.y * 128;
    const int mg    = blockIdx.y;

    const int lrow_a = ((lane >> 3) & 1) * 8 + (lane & 7);
    const int lrow_b = (lane >> 4) * 8 + (lane & 7);
    const int lxor   = lane & 7;
    const int ahalf  = lane >> 4;
    const int bhalf  = (lane >> 3) & 1;

    // ---- one-time W_hh preload: 16 chunks x 64 rows x 128B, swizzled ----
#pragma unroll
    for (int c = 0; c < 16; c++) {
        const char* Bs = (const char*)(whh + ((size_t)c * 4096 + nBase) * 64);
#pragma unroll
        for (int q = 0; q < 2; q++) {
            const int e = tid + q * 256;
            const int r = e >> 3, s = e & 7;
            const uint32_t off = r * 128 + (((uint32_t)(s ^ (r & 7))) << 4);
            cp_async16(sbase + SM_W + c * 8192u + off, Bs + r * 128 + s * 16);
        }
    }
    cp_commit();

    // per-thread persistent cell state + output weights
    const int bloc = tid >> 1;
    const int b = mBase + bloc;
    const int jh = (tid & 1) * 8;
    const int j0 = (nBase >> 2) + jh;
    float cc[8], wout[8];
#pragma unroll
    for (int jj = 0; jj < 8; jj++) {
        cc[jj]   = c0[b * HH + j0 + jj];
        wout[jj] = W_out[j0 + jj];
    }

    volatile int* barp = &g_bar[mg];
    cp_wait<0>();
    __syncthreads();

    for (int t = 0; t < TT; t++) {
        const __half* hcR = (t & 1) ? hc1 : hc0;
        __half*       hcW = (t & 1) ? hc0 : hc1;
        const float*  xg_t = xg + (size_t)t * BB * GG;

        // prefetch this thread's xg slice
        float4 xr[8];
        const float4* xp = (const float4*)(xg_t + (size_t)b * GG + nBase) + jh;
#pragma unroll
        for (int jj = 0; jj < 8; jj++) xr[jj] = xp[jj];

        float c[2][4][4];
#pragma unroll
        for (int i = 0; i < 2; i++)
#pragma unroll
            for (int j = 0; j < 4; j++)
#pragma unroll
                for (int k = 0; k < 4; k++) c[i][j][k] = 0.0f;

        // prefetch A chunks 0..2 (depth-4 pipeline)
#pragma unroll
        for (int p = 0; p < 3; p++) {
            LOAD_A(hcR, mBase, p, sbase + SM_A + (uint32_t)p * 16384u);
            cp_commit();
        }

        for (int i = 0; i < 16; i++) {
            // wait for group i: outstanding after issues = {i+1,i+2,i+3} at most
            if (i <= 13)      cp_wait<2>();
            else if (i == 14) cp_wait<1>();
            else              cp_wait<0>();
            __syncthreads();
            if (i + 3 < 16) {
                LOAD_A(hcR, mBase, i + 3, sbase + SM_A + (uint32_t)((i + 3) & 3) * 16384u);
                cp_commit();
            }

            const uint32_t aTile = sbase + SM_A + (uint32_t)(i & 3) * 16384u;
            const uint32_t bTile = sbase + SM_W + (uint32_t)i * 8192u;
#pragma unroll
            for (int kk = 0; kk < 4; kk++) {
                uint32_t a[2][4], bfrag[4][2];
#pragma unroll
                for (int mt = 0; mt < 2; mt++) {
                    const int row = wm * 32 + mt * 16 + lrow_a;
                    const uint32_t addr = aTile + row * 128 +
                        (((uint32_t)((kk * 2 + ahalf) ^ lxor)) << 4);
                    ldsm_x4(a[mt][0], a[mt][1], a[mt][2], a[mt][3], addr);
                }
#pragma unroll
                for (int bt = 0; bt < 2; bt++) {
                    const int row = wn * 32 + bt * 16 + lrow_b;
                    const uint32_t addr = bTile + row * 128 +
                        (((uint32_t)((kk * 2 + bhalf) ^ lxor)) << 4);
                    uint32_t r0, r1, r2, r3;
                    ldsm_x4(r0, r1, r2, r3, addr);
                    bfrag[2 * bt][0] = r0;     bfrag[2 * bt][1] = r1;
                    bfrag[2 * bt + 1][0] = r2; bfrag[2 * bt + 1][1] = r3;
                }
#pragma unroll
                for (int mt = 0; mt < 2; mt++)
#pragma unroll
                    for (int nt = 0; nt < 4; nt++)
                        mma16816(c[mt][nt], a[mt], bfrag[nt]);
            }
        }

        // stage MMA result into smem
        const int g  = lane >> 2;
        const int tg = lane & 3;
#pragma unroll
        for (int mt = 0; mt < 2; mt++) {
#pragma unroll
            for (int nt = 0; nt < 4; nt++) {
                const int col = wn * 32 + nt * 8 + tg * 2;
#pragma unroll
                for (int half = 0; half < 2; half++) {
                    const int row = wm * 32 + mt * 16 + g + half * 8;
                    gate_sm[row * GATE_W + col]     = c[mt][nt][half * 2 + 0];
                    gate_sm[row * GATE_W + col + 1] = c[mt][nt][half * 2 + 1];
                }
            }
        }
        __syncthreads();

        // cell math (c in registers across steps)
        float osum = 0.0f;
#pragma unroll
        for (int jj = 0; jj < 8; jj++) {
            const int jloc = jh + jj;
            const int j = (nBase >> 2) + jloc;
            const float4 mm = *(const float4*)&gate_sm[bloc * GATE_W + jloc * 4];
            const float ig = sigf(mm.x + xr[jj].x);
            const float fg = sigf(mm.y + xr[jj].y);
            const float gg = tanhf(mm.z + xr[jj].z);
            const float og = sigf(mm.w + xr[jj].w);
            cc[jj] = fg * cc[jj] + ig * gg;
            const float h = og * tanhf(cc[jj]);

            const int chunk = j >> 6, col = j & 63;
            hcW[((size_t)chunk * BB + b) * 64 + col] = __float2half_rn(h);
            osum += h * wout[jj];
            if (t == TT - 1) { hT[b * HH + j] = h; cT[b * HH + j] = cc[jj]; }
        }
        // pair-combine (tid even/odd share b) then single atomic
        osum += __shfl_xor_sync(0xFFFFFFFFu, osum, 1);
        if ((tid & 1) == 0) atomicAdd(&out[t * BB + b], osum);

        // per-m-group step barrier (tid-0 spin only)
        __threadfence();
        __syncthreads();
        if (tid == 0) {
            atomicAdd(&g_bar[mg], 1);
            const int target = 64 * (t + 1);
            while (*barp < target) { __nanosleep(64); }
        }
        __syncthreads();
        __threadfence();
    }
}

// ===================== conversion / pointwise kernels ========================
__global__ void split_hi_k(const float* __restrict__ src, __half* __restrict__ dst,
                           int R, int K)
{
    const size_t i = (size_t)blockIdx.x * blockDim.x + threadIdx.x;
    const int r = (int)(i / K);
    const int k = (int)(i - (size_t)r * K);
    const int chunk = k >> 6, col = k & 63;
    dst[((size_t)chunk * R + r) * 64 + col] = __float2half_rn(src[i]);
}

__global__ void split_perm_hi_k(const float* __restrict__ src, __half* __restrict__ dst)
{
    const size_t i = (size_t)blockIdx.x * blockDim.x + threadIdx.x;
    const int r = (int)(i >> 10);
    const int k = (int)(i & 1023);
    const int gt = r >> 10, j = r & 1023;
    const int rp = j * 4 + gt;
    const int chunk = k >> 6, col = k & 63;
    dst[((size_t)chunk * 4096 + rp) * 64 + col] = __float2half_rn(src[i]);
}

// merged setup: bias combine + h0 convert + out init + barrier reset
__global__ void setup_k(const float* __restrict__ b_ih, const float* __restrict__ b_hh,
                        const float* __restrict__ h0,
                        float* __restrict__ out, const float* __restrict__ b_out)
{
    const int i = blockIdx.x * blockDim.x + threadIdx.x;  // [0, B*H)
    if (i < 2) g_bar[i] = 0;
    if (i < GG) {
        const int gt = i & 3, j = i >> 2;
        const int s = gt * HH + j;
        g_bias[i] = b_ih[s] + b_hh[s];
    }
    if (i < TT * BB) out[i] = b_out[0];
    const int b = i >> 10, j = i & 1023;
    const int chunk = j >> 6, col = j & 63;
    g_hc[((size_t)chunk * BB + b) * 64 + col] = __float2half_rn(h0[i]);
}

// ===================== launch ================================================
#define SMEM_BIG 65536

extern "C" void kernel_launch(void* const* d_in, const int* in_sizes, int n_in,
                              void* d_out, int out_size)
{
    const float* inputs = (const float*)d_in[0];
    const float* h0     = (const float*)d_in[1];
    const float* c0     = (const float*)d_in[2];
    const float* W1     = (const float*)d_in[3];
    const float* b1     = (const float*)d_in[4];
    const float* W_ih   = (const float*)d_in[5];
    const float* W_hh   = (const float*)d_in[6];
    const float* b_ih   = (const float*)d_in[7];
    const float* b_hh   = (const float*)d_in[8];
    const float* W_out  = (const float*)d_in[9];
    const float* b_out  = (const float*)d_in[10];

    float* out = (float*)d_out;
    float* hT  = out + TT * BB;
    float* cT  = hT + BB * HH;

    __half *pinc, *pxc, *pw1c, *pwihc, *pwhhc, *phc;
    float *pxg, *pbias;
    cudaGetSymbolAddress((void**)&pinc,  g_inc);
    cudaGetSymbolAddress((void**)&pxc,   g_xc);
    cudaGetSymbolAddress((void**)&pw1c,  g_w1c);
    cudaGetSymbolAddress((void**)&pwihc, g_wihc);
    cudaGetSymbolAddress((void**)&pwhhc, g_whhc);
    cudaGetSymbolAddress((void**)&phc,   g_hc);
    cudaGetSymbolAddress((void**)&pxg,   g_xg);
    cudaGetSymbolAddress((void**)&pbias, g_bias);

    cudaFuncSetAttribute((const void*)gemm_mma<0>, cudaFuncAttributeMaxDynamicSharedMemorySize, SMEM_BIG);
    cudaFuncSetAttribute((const void*)gemm_mma<1>, cudaFuncAttributeMaxDynamicSharedMemorySize, SMEM_BIG);
    cudaFuncSetAttribute((const void*)rec_persist_k, cudaFuncAttributeMaxDynamicSharedMemorySize, SMEM_REC);

    // conversions (all hi-only)
    split_hi_k<<<(32768 * 512) / 256, 256>>>(inputs, pinc, 32768, 512);
    split_hi_k<<<(1024 * 512) / 256, 256>>>(W1, pw1c, 1024, 512);
    split_perm_hi_k<<<(4096 * 1024) / 256, 256>>>(W_ih, pwihc);
    split_perm_hi_k<<<(4096 * 1024) / 256, 256>>>(W_hh, pwhhc);
    setup_k<<<(BB * HH) / 256, 256>>>(b_ih, b_hh, h0, out, b_out);

    // GEMM1: x = relu(inputs @ W1^T + b1) -> hi store g_xc  (1-pass, C=8)
    {
        dim3 grid(HH / 128, 32768 / 128);
        gemm_mma<0><<<grid, 256, SMEM_BIG>>>(pinc, pw1c, b1, nullptr, pxc, 32768, HH, 8);
    }
    // GEMM2: xg' = x_hi @ W_ih_hi'^T + bias' -> g_xg  (1-pass, C=16)
    {
        dim3 grid(GG / 128, 32768 / 128);
        gemm_mma<1><<<grid, 256, SMEM_BIG>>>(pxc, pwihc, pbias, pxg, nullptr, 32768, GG, 16);
    }
    // persistent recurrence: 128 co-resident CTAs, smem-resident W, 4-deep pipe
    {
        dim3 grid(GG / 64, BB / 128);
        rec_persist_k<<<grid, 256, SMEM_REC>>>(phc, phc + HSPLIT, pwhhc, pxg,
                                               W_out, c0, out, hT, cT);
    }
}

// round 14
// speedup vs baseline: 1.4434x; 1.0060x over previous
#include <cuda_runtime.h>
#include <cuda_fp16.h>
#include <math.h>
#include <stdint.h>

#define TT 128
#define BB 256
#define DD 512
#define HH 1024
#define GG 4096   // 4*H

// ===================== scratch (static device globals) ======================
__device__ __align__(16) __half g_inc [(size_t)8  * 32768 * 64]; // inputs hi (C=8)
__device__ __align__(16) __half g_xc  [(size_t)16 * 32768 * 64]; // x hi      (C=16)
__device__ __align__(16) __half g_w1c [(size_t)8  * 1024  * 64]; // W1 hi
__device__ __align__(16) __half g_wihc[(size_t)16 * 4096  * 64]; // W_ih hi (gate-perm)
__device__ __align__(16) __half g_whhc[(size_t)16 * 4096  * 64]; // W_hh hi (gate-perm)
#define HSPLIT ((size_t)16 * 256 * 64)
__device__ __align__(16) __half g_hc  [2 * HSPLIT];              // h hi, ping-pong
__device__ __align__(16) float g_xg[(size_t)TT * BB * GG];       // gate-perm cols
__device__ __align__(16) float g_bias[GG];                       // gate-perm
__device__ int g_bar[2];                                         // per-m-group step barrier

// ===================== PTX helpers ==========================================
__device__ __forceinline__ uint32_t smem_u32(const void* p) {
    return (uint32_t)__cvta_generic_to_shared(p);
}
__device__ __forceinline__ void cp_async16(uint32_t dst, const void* src) {
    asm volatile("cp.async.cg.shared.global [%0], [%1], 16;" :: "r"(dst), "l"(src));
}
__device__ __forceinline__ void cp_commit() {
    asm volatile("cp.async.commit_group;" ::: "memory");
}
template<int N>
__device__ __forceinline__ void cp_wait() {
    asm volatile("cp.async.wait_group %0;" :: "n"(N) : "memory");
}
__device__ __forceinline__ void ldsm_x4(uint32_t& r0, uint32_t& r1, uint32_t& r2, uint32_t& r3,
                                        uint32_t addr) {
    asm volatile("ldmatrix.sync.aligned.m8n8.x4.shared.b16 {%0,%1,%2,%3}, [%4];"
                 : "=r"(r0), "=r"(r1), "=r"(r2), "=r"(r3) : "r"(addr));
}
__device__ __forceinline__ void mma16816(float* c, const uint32_t* a, const uint32_t* b) {
    asm volatile(
        "mma.sync.aligned.m16n8k16.row.col.f32.f16.f16.f32 "
        "{%0,%1,%2,%3}, {%4,%5,%6,%7}, {%8,%9}, {%0,%1,%2,%3};"
        : "+f"(c[0]), "+f"(c[1]), "+f"(c[2]), "+f"(c[3])
        : "r"(a[0]), "r"(a[1]), "r"(a[2]), "r"(a[3]), "r"(b[0]), "r"(b[1]));
}

__device__ __forceinline__ void store_hi(__half* dst, int M, int m, int n, float v) {
    const int chunk = n >> 6, col = n & 63;
    dst[((size_t)chunk * M + m) * 64 + col] = __float2half_rn(v);
}

// chunk loader: A tile RA rows, B tile RB rows, 128B rows, XOR-swizzled
#define LOAD_CHUNK(A_, B_, M_, N_, mB_, nB_, RA_, RB_, ac_, bc_, dA_)             \
    do {                                                                          \
        const char* As_ = (const char*)((A_) + ((size_t)(ac_) * (M_) + (mB_)) * 64);\
        const char* Bs_ = (const char*)((B_) + ((size_t)(bc_) * (N_) + (nB_)) * 64);\
        const uint32_t dB_ = (dA_) + (RA_) * 128u;                                \
        _Pragma("unroll")                                                         \
        for (int q_ = 0; q_ < (RA_) / 32; q_++) {                                 \
            const int e_ = tid + q_ * 256;                                        \
            const int r_ = e_ >> 3, s_ = e_ & 7;                                  \
            const uint32_t off_ = r_ * 128 + (((uint32_t)(s_ ^ (r_ & 7))) << 4);  \
            cp_async16((dA_) + off_, As_ + r_ * 128 + s_ * 16);                   \
        }                                                                         \
        _Pragma("unroll")                                                         \
        for (int q_ = 0; q_ < (RB_) / 32; q_++) {                                 \
            const int e_ = tid + q_ * 256;                                        \
            const int r_ = e_ >> 3, s_ = e_ & 7;                                  \
            const uint32_t off_ = r_ * 128 + (((uint32_t)(s_ ^ (r_ & 7))) << 4);  \
            cp_async16(dB_ + off_, Bs_ + r_ * 128 + s_ * 16);                     \
        }                                                                         \
    } while (0)

// A-only loader (128 rows)
#define LOAD_A(A_, mB_, ac_, dA_)                                                 \
    do {                                                                          \
        const char* As_ = (const char*)((A_) + ((size_t)(ac_) * 256 + (mB_)) * 64);\
        _Pragma("unroll")                                                         \
        for (int q_ = 0; q_ < 4; q_++) {                                          \
            const int e_ = tid + q_ * 256;                                        \
            const int r_ = e_ >> 3, s_ = e_ & 7;                                  \
            const uint32_t off_ = r_ * 128 + (((uint32_t)(s_ ^ (r_ & 7))) << 4);  \
            cp_async16((dA_) + off_, As_ + r_ * 128 + s_ * 16);                   \
        }                                                                         \
    } while (0)

// ===================== big GEMMs (BM=BN=128, 3-stage single-sync, 2 CTA/SM) ==
// MODE 0: v=relu(v+aux[n]) -> hi store; MODE 1: v=v+aux[n] -> outF
template<int MODE>
__global__ __launch_bounds__(256, 2)
void gemm_mma(const __half* __restrict__ A, const __half* __restrict__ B,
              const float* __restrict__ aux, float* __restrict__ outF,
              __half* __restrict__ outSplit, int M, int N, int C)
{
    extern __shared__ char smraw[];
    const uint32_t sbase = smem_u32(smraw);   // 3 stages x (A 16KB | B 16KB)

    const int tid  = threadIdx.x;
    const int lane = tid & 31;
    const int wid  = tid >> 5;
    const int wm   = wid & 3;
    const int wn   = wid >> 2;
    const int mBase = blockIdx.y * 128;
    const int nBase = blockIdx.x * 128;
    const int NIT = C;

    float c[2][8][4];
#pragma unroll
    for (int i = 0; i < 2; i++)
#pragma unroll
        for (int j = 0; j < 8; j++)
#pragma unroll
            for (int k = 0; k < 4; k++) c[i][j][k] = 0.0f;

    const int lrow_a = ((lane >> 3) & 1) * 8 + (lane & 7);
    const int lrow_b = (lane >> 4) * 8 + (lane & 7);
    const int lxor   = lane & 7;
    const int ahalf  = lane >> 4;
    const int bhalf  = (lane >> 3) & 1;

    // prefetch stages 0,1 (scalar rotating offsets; no arrays)
    LOAD_CHUNK(A, B, M, N, mBase, nBase, 128, 128, 0, 0, sbase);
    cp_commit();
    LOAD_CHUNK(A, B, M, N, mBase, nBase, 128, 128, 1, 1, sbase + 32768u);
    cp_commit();

    uint32_t curOff = 0u, nxtOff = 65536u;   // buf(i)%3*32768 ; buf(i+2)%3*32768
    for (int i = 0; i < NIT; i++) {
        if (i == NIT - 1) cp_wait<0>(); else cp_wait<1>();
        __syncthreads();                      // compute(i-1) done -> buf(i+2) free
        if (i + 2 < NIT) {
            LOAD_CHUNK(A, B, M, N, mBase, nBase, 128, 128, i + 2, i + 2, sbase + nxtOff);
            cp_commit();
        }

        const uint32_t aTile = sbase + curOff;
        const uint32_t bTile = aTile + 16384u;
        // rotate: cur advances by 32768 mod 98304; nxt likewise
        curOff = (curOff == 65536u) ? 0u : curOff + 32768u;
        nxtOff = (nxtOff == 65536u) ? 0u : nxtOff + 32768u;
#pragma unroll
        for (int kk = 0; kk < 4; kk++) {
            uint32_t a[2][4], b[8][2];
#pragma unroll
            for (int mt = 0; mt < 2; mt++) {
                const int row = wm * 32 + mt * 16 + lrow_a;
                const uint32_t addr = aTile + row * 128 +
                    (((uint32_t)((kk * 2 + ahalf) ^ lxor)) << 4);
                ldsm_x4(a[mt][0], a[mt][1], a[mt][2], a[mt][3], addr);
            }
#pragma unroll
            for (int bt = 0; bt < 4; bt++) {
                const int row = wn * 64 + bt * 16 + lrow_b;
                const uint32_t addr = bTile + row * 128 +
                    (((uint32_t)((kk * 2 + bhalf) ^ lxor)) << 4);
                uint32_t r0, r1, r2, r3;
                ldsm_x4(r0, r1, r2, r3, addr);
                b[2 * bt][0] = r0;     b[2 * bt][1] = r1;
                b[2 * bt + 1][0] = r2; b[2 * bt + 1][1] = r3;
            }
#pragma unroll
            for (int mt = 0; mt < 2; mt++)
#pragma unroll
                for (int nt = 0; nt < 8; nt++)
                    mma16816(c[mt][nt], a[mt], b[nt]);
        }
    }

    const int g  = lane >> 2;
    const int tg = lane & 3;
#pragma unroll
    for (int mt = 0; mt < 2; mt++) {
        const int m0 = mBase + wm * 32 + mt * 16 + g;
#pragma unroll
        for (int nt = 0; nt < 8; nt++) {
            const int n0 = nBase + wn * 64 + nt * 8 + tg * 2;
#pragma unroll
            for (int half = 0; half < 2; half++) {
                const int m = m0 + half * 8;
                const float v0 = c[mt][nt][half * 2 + 0];
                const float v1 = c[mt][nt][half * 2 + 1];
                if (MODE == 0) {
                    store_hi(outSplit, M, m, n0,     fmaxf(v0 + aux[n0],     0.0f));
                    store_hi(outSplit, M, m, n0 + 1, fmaxf(v1 + aux[n0 + 1], 0.0f));
                } else {
                    float2 r = make_float2(v0 + aux[n0], v1 + aux[n0 + 1]);
                    *(float2*)(outF + (size_t)m * N + n0) = r;
                }
            }
        }
    }
}

// ===================== persistent fused recurrence ===========================
// W_hh resident in smem; 4-deep A pipeline, ONE syncthreads/iter;
// per-m-group barrier (64 arrivals).
// smem: [0,128K) W | [128K,192K) A x4 | [192K,+34.8K) gates  -> 231424 B
#define GATE_W 68
#define SM_W    0u
#define SM_A    131072u
#define SM_GATE 196608u
#define SMEM_REC (196608 + 128 * GATE_W * 4)

__device__ __forceinline__ float sigf(float x) { return 1.0f / (1.0f + __expf(-x)); }

__global__ __launch_bounds__(256, 1)
void rec_persist_k(__half* __restrict__ hc0, __half* __restrict__ hc1,
                   const __half* __restrict__ whh, const float* __restrict__ xg,
                   const float* __restrict__ W_out, const float* __restrict__ c0,
                   float* __restrict__ out, float* __restrict__ hT, float* __restrict__ cT)
{
    extern __shared__ char smraw[];
    const uint32_t sbase = smem_u32(smraw);
    float* gate_sm = (float*)(smraw + SM_GATE);

    const int tid  = threadIdx.x;
    const int lane = tid & 31;
    const int wid  = tid >> 5;
    const int wm   = wid & 3;
    const int wn   = wid >> 2;
    const int nBase = blockIdx.x * 64;
    const int mBase = blockIdx.y * 128;
    const int mg    = blockIdx.y;

    const int lrow_a = ((lane >> 3) & 1) * 8 + (lane & 7);
    const int lrow_b = (lane >> 4) * 8 + (lane & 7);
    const int lxor   = lane & 7;
    const int ahalf  = lane >> 4;
    const int bhalf  = (lane >> 3) & 1;

    // ---- one-time W_hh preload: 16 chunks x 64 rows x 128B, swizzled ----
#pragma unroll
    for (int c = 0; c < 16; c++) {
        const char* Bs = (const char*)(whh + ((size_t)c * 4096 + nBase) * 64);
#pragma unroll
        for (int q = 0; q < 2; q++) {
            const int e = tid + q * 256;
            const int r = e >> 3, s = e & 7;
            const uint32_t off = r * 128 + (((uint32_t)(s ^ (r & 7))) << 4);
            cp_async16(sbase + SM_W + c * 8192u + off, Bs + r * 128 + s * 16);
        }
    }
    cp_commit();

    // per-thread persistent cell state + output weights
    const int bloc = tid >> 1;
    const int b = mBase + bloc;
    const int jh = (tid & 1) * 8;
    const int j0 = (nBase >> 2) + jh;
    float cc[8], wout[8];
#pragma unroll
    for (int jj = 0; jj < 8; jj++) {
        cc[jj]   = c0[b * HH + j0 + jj];
        wout[jj] = W_out[j0 + jj];
    }

    volatile int* barp = &g_bar[mg];
    cp_wait<0>();
    __syncthreads();

    for (int t = 0; t < TT; t++) {
        const __half* hcR = (t & 1) ? hc1 : hc0;
        __half*       hcW = (t & 1) ? hc0 : hc1;
        const float*  xg_t = xg + (size_t)t * BB * GG;

        // prefetch this thread's xg slice
        float4 xr[8];
        const float4* xp = (const float4*)(xg_t + (size_t)b * GG + nBase) + jh;
#pragma unroll
        for (int jj = 0; jj < 8; jj++) xr[jj] = xp[jj];

        float c[2][4][4];
#pragma unroll
        for (int i = 0; i < 2; i++)
#pragma unroll
            for (int j = 0; j < 4; j++)
#pragma unroll
                for (int k = 0; k < 4; k++) c[i][j][k] = 0.0f;

        // prefetch A chunks 0..2 (depth-4 pipeline)
#pragma unroll
        for (int p = 0; p < 3; p++) {
            LOAD_A(hcR, mBase, p, sbase + SM_A + (uint32_t)p * 16384u);
            cp_commit();
        }

        for (int i = 0; i < 16; i++) {
            if (i <= 13)      cp_wait<2>();
            else if (i == 14) cp_wait<1>();
            else              cp_wait<0>();
            __syncthreads();
            if (i + 3 < 16) {
                LOAD_A(hcR, mBase, i + 3, sbase + SM_A + (uint32_t)((i + 3) & 3) * 16384u);
                cp_commit();
            }

            const uint32_t aTile = sbase + SM_A + (uint32_t)(i & 3) * 16384u;
            const uint32_t bTile = sbase + SM_W + (uint32_t)i * 8192u;
#pragma unroll
            for (int kk = 0; kk < 4; kk++) {
                uint32_t a[2][4], bfrag[4][2];
#pragma unroll
                for (int mt = 0; mt < 2; mt++) {
                    const int row = wm * 32 + mt * 16 + lrow_a;
                    const uint32_t addr = aTile + row * 128 +
                        (((uint32_t)((kk * 2 + ahalf) ^ lxor)) << 4);
                    ldsm_x4(a[mt][0], a[mt][1], a[mt][2], a[mt][3], addr);
                }
#pragma unroll
                for (int bt = 0; bt < 2; bt++) {
                    const int row = wn * 32 + bt * 16 + lrow_b;
                    const uint32_t addr = bTile + row * 128 +
                        (((uint32_t)((kk * 2 + bhalf) ^ lxor)) << 4);
                    uint32_t r0, r1, r2, r3;
                    ldsm_x4(r0, r1, r2, r3, addr);
                    bfrag[2 * bt][0] = r0;     bfrag[2 * bt][1] = r1;
                    bfrag[2 * bt + 1][0] = r2; bfrag[2 * bt + 1][1] = r3;
                }
#pragma unroll
                for (int mt = 0; mt < 2; mt++)
#pragma unroll
                    for (int nt = 0; nt < 4; nt++)
                        mma16816(c[mt][nt], a[mt], bfrag[nt]);
            }
        }

        // stage MMA result into smem
        const int g  = lane >> 2;
        const int tg = lane & 3;
#pragma unroll
        for (int mt = 0; mt < 2; mt++) {
#pragma unroll
            for (int nt = 0; nt < 4; nt++) {
                const int col = wn * 32 + nt * 8 + tg * 2;
#pragma unroll
                for (int half = 0; half < 2; half++) {
                    const int row = wm * 32 + mt * 16 + g + half * 8;
                    gate_sm[row * GATE_W + col]     = c[mt][nt][half * 2 + 0];
                    gate_sm[row * GATE_W + col + 1] = c[mt][nt][half * 2 + 1];
                }
            }
        }
        __syncthreads();

        // cell math (c in registers across steps)
        float osum = 0.0f;
#pragma unroll
        for (int jj = 0; jj < 8; jj++) {
            const int jloc = jh + jj;
            const int j = (nBase >> 2) + jloc;
            const float4 mm = *(const float4*)&gate_sm[bloc * GATE_W + jloc * 4];
            const float ig = sigf(mm.x + xr[jj].x);
            const float fg = sigf(mm.y + xr[jj].y);
            const float gg = tanhf(mm.z + xr[jj].z);
            const float og = sigf(mm.w + xr[jj].w);
            cc[jj] = fg * cc[jj] + ig * gg;
            const float h = og * tanhf(cc[jj]);

            const int chunk = j >> 6, col = j & 63;
            hcW[((size_t)chunk * BB + b) * 64 + col] = __float2half_rn(h);
            osum += h * wout[jj];
            if (t == TT - 1) { hT[b * HH + j] = h; cT[b * HH + j] = cc[jj]; }
        }
        osum += __shfl_xor_sync(0xFFFFFFFFu, osum, 1);
        if ((tid & 1) == 0) atomicAdd(&out[t * BB + b], osum);

        // per-m-group step barrier (tid-0 spin only)
        __threadfence();
        __syncthreads();
        if (tid == 0) {
            atomicAdd(&g_bar[mg], 1);
            const int target = 64 * (t + 1);
            while (*barp < target) { __nanosleep(64); }
        }
        __syncthreads();
        __threadfence();
    }
}

// ===================== conversion / pointwise kernels ========================
__global__ void split_hi_k(const float* __restrict__ src, __half* __restrict__ dst,
                           int R, int K)
{
    const size_t i = (size_t)blockIdx.x * blockDim.x + threadIdx.x;
    const int r = (int)(i / K);
    const int k = (int)(i - (size_t)r * K);
    const int chunk = k >> 6, col = k & 63;
    dst[((size_t)chunk * R + r) * 64 + col] = __float2half_rn(src[i]);
}

__global__ void split_perm_hi_k(const float* __restrict__ src, __half* __restrict__ dst)
{
    const size_t i = (size_t)blockIdx.x * blockDim.x + threadIdx.x;
    const int r = (int)(i >> 10);
    const int k = (int)(i & 1023);
    const int gt = r >> 10, j = r & 1023;
    const int rp = j * 4 + gt;
    const int chunk = k >> 6, col = k & 63;
    dst[((size_t)chunk * 4096 + rp) * 64 + col] = __float2half_rn(src[i]);
}

// merged setup: bias combine + h0 convert + out init + barrier reset
__global__ void setup_k(const float* __restrict__ b_ih, const float* __restrict__ b_hh,
                        const float* __restrict__ h0,
                        float* __restrict__ out, const float* __restrict__ b_out)
{
    const int i = blockIdx.x * blockDim.x + threadIdx.x;  // [0, B*H)
    if (i < 2) g_bar[i] = 0;
    if (i < GG) {
        const int gt = i & 3, j = i >> 2;
        const int s = gt * HH + j;
        g_bias[i] = b_ih[s] + b_hh[s];
    }
    if (i < TT * BB) out[i] = b_out[0];
    const int b = i >> 10, j = i & 1023;
    const int chunk = j >> 6, col = j & 63;
    g_hc[((size_t)chunk * BB + b) * 64 + col] = __float2half_rn(h0[i]);
}

// ===================== launch ================================================
#define SMEM_BIG 98304

extern "C" void kernel_launch(void* const* d_in, const int* in_sizes, int n_in,
                              void* d_out, int out_size)
{
    const float* inputs = (const float*)d_in[0];
    const float* h0     = (const float*)d_in[1];
    const float* c0     = (const float*)d_in[2];
    const float* W1     = (const float*)d_in[3];
    const float* b1     = (const float*)d_in[4];
    const float* W_ih   = (const float*)d_in[5];
    const float* W_hh   = (const float*)d_in[6];
    const float* b_ih   = (const float*)d_in[7];
    const float* b_hh   = (const float*)d_in[8];
    const float* W_out  = (const float*)d_in[9];
    const float* b_out  = (const float*)d_in[10];

    float* out = (float*)d_out;
    float* hT  = out + TT * BB;
    float* cT  = hT + BB * HH;

    __half *pinc, *pxc, *pw1c, *pwihc, *pwhhc, *phc;
    float *pxg, *pbias;
    cudaGetSymbolAddress((void**)&pinc,  g_inc);
    cudaGetSymbolAddress((void**)&pxc,   g_xc);
    cudaGetSymbolAddress((void**)&pw1c,  g_w1c);
    cudaGetSymbolAddress((void**)&pwihc, g_wihc);
    cudaGetSymbolAddress((void**)&pwhhc, g_whhc);
    cudaGetSymbolAddress((void**)&phc,   g_hc);
    cudaGetSymbolAddress((void**)&pxg,   g_xg);
    cudaGetSymbolAddress((void**)&pbias, g_bias);

    cudaFuncSetAttribute((const void*)gemm_mma<0>, cudaFuncAttributeMaxDynamicSharedMemorySize, SMEM_BIG);
    cudaFuncSetAttribute((const void*)gemm_mma<1>, cudaFuncAttributeMaxDynamicSharedMemorySize, SMEM_BIG);
    cudaFuncSetAttribute((const void*)rec_persist_k, cudaFuncAttributeMaxDynamicSharedMemorySize, SMEM_REC);

    // conversions (all hi-only)
    split_hi_k<<<(32768 * 512) / 256, 256>>>(inputs, pinc, 32768, 512);
    split_hi_k<<<(1024 * 512) / 256, 256>>>(W1, pw1c, 1024, 512);
    split_perm_hi_k<<<(4096 * 1024) / 256, 256>>>(W_ih, pwihc);
    split_perm_hi_k<<<(4096 * 1024) / 256, 256>>>(W_hh, pwhhc);
    setup_k<<<(BB * HH) / 256, 256>>>(b_ih, b_hh, h0, out, b_out);

    // GEMM1: x = relu(inputs @ W1^T + b1) -> hi store g_xc  (1-pass, C=8)
    {
        dim3 grid(HH / 128, 32768 / 128);
        gemm_mma<0><<<grid, 256, SMEM_BIG>>>(pinc, pw1c, b1, nullptr, pxc, 32768, HH, 8);
    }
    // GEMM2: xg' = x_hi @ W_ih_hi'^T + bias' -> g_xg  (1-pass, C=16)
    {
        dim3 grid(GG / 128, 32768 / 128);
        gemm_mma<1><<<grid, 256, SMEM_BIG>>>(pxc, pwihc, pbias, pxg, nullptr, 32768, GG, 16);
    }
    // persistent recurrence: 128 co-resident CTAs, smem-resident W, 4-deep pipe
    {
        dim3 grid(GG / 64, BB / 128);
        rec_persist_k<<<grid, 256, SMEM_REC>>>(phc, phc + HSPLIT, pwhhc, pxg,
                                               W_out, c0, out, hT, cT);
    }
}

// round 15
// speedup vs baseline: 1.4604x; 1.0118x over previous
#include <cuda_runtime.h>
#include <cuda_fp16.h>
#include <math.h>
#include <stdint.h>

#define TT 128
#define BB 256
#define DD 512
#define HH 1024
#define GG 4096   // 4*H

// ===================== scratch (static device globals) ======================
__device__ __align__(16) __half g_inc [(size_t)8  * 32768 * 64]; // inputs hi (C=8)
__device__ __align__(16) __half g_xc  [(size_t)16 * 32768 * 64]; // x hi      (C=16)
__device__ __align__(16) __half g_w1c [(size_t)8  * 1024  * 64]; // W1 hi
__device__ __align__(16) __half g_wihc[(size_t)16 * 4096  * 64]; // W_ih hi (gate-perm)
__device__ __align__(16) __half g_whhc[(size_t)16 * 4096  * 64]; // W_hh hi (gate-perm)
#define HSPLIT ((size_t)16 * 256 * 64)
__device__ __align__(16) __half g_hc  [2 * HSPLIT];              // h hi, ping-pong
__device__ __align__(16) float g_xg[(size_t)TT * BB * GG];       // gate-perm cols
__device__ __align__(16) float g_bias[GG];                       // gate-perm
__device__ int g_bar[2];                                         // per-m-group step barrier

// ===================== PTX helpers ==========================================
__device__ __forceinline__ uint32_t smem_u32(const void* p) {
    return (uint32_t)__cvta_generic_to_shared(p);
}
__device__ __forceinline__ void cp_async16(uint32_t dst, const void* src) {
    asm volatile("cp.async.cg.shared.global [%0], [%1], 16;" :: "r"(dst), "l"(src));
}
__device__ __forceinline__ void cp_commit() {
    asm volatile("cp.async.commit_group;" ::: "memory");
}
template<int N>
__device__ __forceinline__ void cp_wait() {
    asm volatile("cp.async.wait_group %0;" :: "n"(N) : "memory");
}
__device__ __forceinline__ void ldsm_x4(uint32_t& r0, uint32_t& r1, uint32_t& r2, uint32_t& r3,
                                        uint32_t addr) {
    asm volatile("ldmatrix.sync.aligned.m8n8.x4.shared.b16 {%0,%1,%2,%3}, [%4];"
                 : "=r"(r0), "=r"(r1), "=r"(r2), "=r"(r3) : "r"(addr));
}
__device__ __forceinline__ void mma16816(float* c, const uint32_t* a, const uint32_t* b) {
    asm volatile(
        "mma.sync.aligned.m16n8k16.row.col.f32.f16.f16.f32 "
        "{%0,%1,%2,%3}, {%4,%5,%6,%7}, {%8,%9}, {%0,%1,%2,%3};"
        : "+f"(c[0]), "+f"(c[1]), "+f"(c[2]), "+f"(c[3])
        : "r"(a[0]), "r"(a[1]), "r"(a[2]), "r"(a[3]), "r"(b[0]), "r"(b[1]));
}

__device__ __forceinline__ void store_hi(__half* dst, int M, int m, int n, float v) {
    const int chunk = n >> 6, col = n & 63;
    dst[((size_t)chunk * M + m) * 64 + col] = __float2half_rn(v);
}

// chunk loader: A tile RA rows, B tile RB rows, 128B rows, XOR-swizzled
#define LOAD_CHUNK(A_, B_, M_, N_, mB_, nB_, RA_, RB_, ac_, bc_, dA_)             \
    do {                                                                          \
        const char* As_ = (const char*)((A_) + ((size_t)(ac_) * (M_) + (mB_)) * 64);\
        const char* Bs_ = (const char*)((B_) + ((size_t)(bc_) * (N_) + (nB_)) * 64);\
        const uint32_t dB_ = (dA_) + (RA_) * 128u;                                \
        _Pragma("unroll")                                                         \
        for (int q_ = 0; q_ < (RA_) / 32; q_++) {                                 \
            const int e_ = tid + q_ * 256;                                        \
            const int r_ = e_ >> 3, s_ = e_ & 7;                                  \
            const uint32_t off_ = r_ * 128 + (((uint32_t)(s_ ^ (r_ & 7))) << 4);  \
            cp_async16((dA_) + off_, As_ + r_ * 128 + s_ * 16);                   \
        }                                                                         \
        _Pragma("unroll")                                                         \
        for (int q_ = 0; q_ < (RB_) / 32; q_++) {                                 \
            const int e_ = tid + q_ * 256;                                        \
            const int r_ = e_ >> 3, s_ = e_ & 7;                                  \
            const uint32_t off_ = r_ * 128 + (((uint32_t)(s_ ^ (r_ & 7))) << 4);  \
            cp_async16(dB_ + off_, Bs_ + r_ * 128 + s_ * 16);                     \
        }                                                                         \
    } while (0)

// A-only loader (128 rows)
#define LOAD_A(A_, mB_, ac_, dA_)                                                 \
    do {                                                                          \
        const char* As_ = (const char*)((A_) + ((size_t)(ac_) * 256 + (mB_)) * 64);\
        _Pragma("unroll")                                                         \
        for (int q_ = 0; q_ < 4; q_++) {                                          \
            const int e_ = tid + q_ * 256;                                        \
            const int r_ = e_ >> 3, s_ = e_ & 7;                                  \
            const uint32_t off_ = r_ * 128 + (((uint32_t)(s_ ^ (r_ & 7))) << 4);  \
            cp_async16((dA_) + off_, As_ + r_ * 128 + s_ * 16);                   \
        }                                                                         \
    } while (0)

// ===================== big GEMMs (BM=BN=128, 3-stage single-sync, 2 CTA/SM) ==
// MODE 0: v=relu(v+aux[n]) -> hi store; MODE 1: v=v+aux[n] -> outF
template<int MODE>
__global__ __launch_bounds__(256, 2)
void gemm_mma(const __half* __restrict__ A, const __half* __restrict__ B,
              const float* __restrict__ aux, float* __restrict__ outF,
              __half* __restrict__ outSplit, int M, int N, int C)
{
    extern __shared__ char smraw[];
    const uint32_t sbase = smem_u32(smraw);   // 3 stages x (A 16KB | B 16KB)

    const int tid  = threadIdx.x;
    const int lane = tid & 31;
    const int wid  = tid >> 5;
    const int wm   = wid & 3;
    const int wn   = wid >> 2;
    const int mBase = blockIdx.y * 128;
    const int nBase = blockIdx.x * 128;
    const int NIT = C;

    float c[2][8][4];
#pragma unroll
    for (int i = 0; i < 2; i++)
#pragma unroll
        for (int j = 0; j < 8; j++)
#pragma unroll
            for (int k = 0; k < 4; k++) c[i][j][k] = 0.0f;

    const int lrow_a = ((lane >> 3) & 1) * 8 + (lane & 7);
    const int lrow_b = (lane >> 4) * 8 + (lane & 7);
    const int lxor   = lane & 7;
    const int ahalf  = lane >> 4;
    const int bhalf  = (lane >> 3) & 1;

    LOAD_CHUNK(A, B, M, N, mBase, nBase, 128, 128, 0, 0, sbase);
    cp_commit();
    LOAD_CHUNK(A, B, M, N, mBase, nBase, 128, 128, 1, 1, sbase + 32768u);
    cp_commit();

    uint32_t curOff = 0u, nxtOff = 65536u;
    for (int i = 0; i < NIT; i++) {
        if (i == NIT - 1) cp_wait<0>(); else cp_wait<1>();
        __syncthreads();
        if (i + 2 < NIT) {
            LOAD_CHUNK(A, B, M, N, mBase, nBase, 128, 128, i + 2, i + 2, sbase + nxtOff);
            cp_commit();
        }

        const uint32_t aTile = sbase + curOff;
        const uint32_t bTile = aTile + 16384u;
        curOff = (curOff == 65536u) ? 0u : curOff + 32768u;
        nxtOff = (nxtOff == 65536u) ? 0u : nxtOff + 32768u;
#pragma unroll
        for (int kk = 0; kk < 4; kk++) {
            uint32_t a[2][4], b[8][2];
#pragma unroll
            for (int mt = 0; mt < 2; mt++) {
                const int row = wm * 32 + mt * 16 + lrow_a;
                const uint32_t addr = aTile + row * 128 +
                    (((uint32_t)((kk * 2 + ahalf) ^ lxor)) << 4);
                ldsm_x4(a[mt][0], a[mt][1], a[mt][2], a[mt][3], addr);
            }
#pragma unroll
            for (int bt = 0; bt < 4; bt++) {
                const int row = wn * 64 + bt * 16 + lrow_b;
                const uint32_t addr = bTile + row * 128 +
                    (((uint32_t)((kk * 2 + bhalf) ^ lxor)) << 4);
                uint32_t r0, r1, r2, r3;
                ldsm_x4(r0, r1, r2, r3, addr);
                b[2 * bt][0] = r0;     b[2 * bt][1] = r1;
                b[2 * bt + 1][0] = r2; b[2 * bt + 1][1] = r3;
            }
#pragma unroll
            for (int mt = 0; mt < 2; mt++)
#pragma unroll
                for (int nt = 0; nt < 8; nt++)
                    mma16816(c[mt][nt], a[mt], b[nt]);
        }
    }

    const int g  = lane >> 2;
    const int tg = lane & 3;
#pragma unroll
    for (int mt = 0; mt < 2; mt++) {
        const int m0 = mBase + wm * 32 + mt * 16 + g;
#pragma unroll
        for (int nt = 0; nt < 8; nt++) {
            const int n0 = nBase + wn * 64 + nt * 8 + tg * 2;
#pragma unroll
            for (int half = 0; half < 2; half++) {
                const int m = m0 + half * 8;
                const float v0 = c[mt][nt][half * 2 + 0];
                const float v1 = c[mt][nt][half * 2 + 1];
                if (MODE == 0) {
                    store_hi(outSplit, M, m, n0,     fmaxf(v0 + aux[n0],     0.0f));
                    store_hi(outSplit, M, m, n0 + 1, fmaxf(v1 + aux[n0 + 1], 0.0f));
                } else {
                    float2 r = make_float2(v0 + aux[n0], v1 + aux[n0 + 1]);
                    *(float2*)(outF + (size_t)m * N + n0) = r;
                }
            }
        }
    }
}

// ===================== persistent fused recurrence ===========================
// W_hh in smem; 4-deep A pipeline, one sync/iter; per-m-group barrier;
// epilogue reordered: h publish + barrier arrive BEFORE out-projection.
#define GATE_W 68
#define SM_W    0u
#define SM_A    131072u
#define SM_GATE 196608u
#define SMEM_REC (196608 + 128 * GATE_W * 4)

__device__ __forceinline__ float sigf(float x) { return 1.0f / (1.0f + __expf(-x)); }

__global__ __launch_bounds__(256, 1)
void rec_persist_k(__half* __restrict__ hc0, __half* __restrict__ hc1,
                   const __half* __restrict__ whh, const float* __restrict__ xg,
                   const float* __restrict__ W_out, const float* __restrict__ c0,
                   float* __restrict__ out, float* __restrict__ hT, float* __restrict__ cT)
{
    extern __shared__ char smraw[];
    const uint32_t sbase = smem_u32(smraw);
    float* gate_sm = (float*)(smraw + SM_GATE);

    const int tid  = threadIdx.x;
    const int lane = tid & 31;
    const int wid  = tid >> 5;
    const int wm   = wid & 3;
    const int wn   = wid >> 2;
    const int nBase = blockIdx.x * 64;
    const int mBase = blockIdx.y * 128;
    const int mg    = blockIdx.y;

    const int lrow_a = ((lane >> 3) & 1) * 8 + (lane & 7);
    const int lrow_b = (lane >> 4) * 8 + (lane & 7);
    const int lxor   = lane & 7;
    const int ahalf  = lane >> 4;
    const int bhalf  = (lane >> 3) & 1;

    // one-time W_hh preload
#pragma unroll
    for (int c = 0; c < 16; c++) {
        const char* Bs = (const char*)(whh + ((size_t)c * 4096 + nBase) * 64);
#pragma unroll
        for (int q = 0; q < 2; q++) {
            const int e = tid + q * 256;
            const int r = e >> 3, s = e & 7;
            const uint32_t off = r * 128 + (((uint32_t)(s ^ (r & 7))) << 4);
            cp_async16(sbase + SM_W + c * 8192u + off, Bs + r * 128 + s * 16);
        }
    }
    cp_commit();

    const int bloc = tid >> 1;
    const int b = mBase + bloc;
    const int jh = (tid & 1) * 8;
    const int j0 = (nBase >> 2) + jh;
    float cc[8], wout[8];
#pragma unroll
    for (int jj = 0; jj < 8; jj++) {
        cc[jj]   = c0[b * HH + j0 + jj];
        wout[jj] = W_out[j0 + jj];
    }

    volatile int* barp = &g_bar[mg];
    cp_wait<0>();
    __syncthreads();

    for (int t = 0; t < TT; t++) {
        const __half* hcR = (t & 1) ? hc1 : hc0;
        __half*       hcW = (t & 1) ? hc0 : hc1;
        const float*  xg_t = xg + (size_t)t * BB * GG;

        float4 xr[8];
        const float4* xp = (const float4*)(xg_t + (size_t)b * GG + nBase) + jh;
#pragma unroll
        for (int jj = 0; jj < 8; jj++) xr[jj] = xp[jj];

        float c[2][4][4];
#pragma unroll
        for (int i = 0; i < 2; i++)
#pragma unroll
            for (int j = 0; j < 4; j++)
#pragma unroll
                for (int k = 0; k < 4; k++) c[i][j][k] = 0.0f;

#pragma unroll
        for (int p = 0; p < 3; p++) {
            LOAD_A(hcR, mBase, p, sbase + SM_A + (uint32_t)p * 16384u);
            cp_commit();
        }

        for (int i = 0; i < 16; i++) {
            if (i <= 13)      cp_wait<2>();
            else if (i == 14) cp_wait<1>();
            else              cp_wait<0>();
            __syncthreads();
            if (i + 3 < 16) {
                LOAD_A(hcR, mBase, i + 3, sbase + SM_A + (uint32_t)((i + 3) & 3) * 16384u);
                cp_commit();
            }

            const uint32_t aTile = sbase + SM_A + (uint32_t)(i & 3) * 16384u;
            const uint32_t bTile = sbase + SM_W + (uint32_t)i * 8192u;
#pragma unroll
            for (int kk = 0; kk < 4; kk++) {
                uint32_t a[2][4], bfrag[4][2];
#pragma unroll
                for (int mt = 0; mt < 2; mt++) {
                    const int row = wm * 32 + mt * 16 + lrow_a;
                    const uint32_t addr = aTile + row * 128 +
                        (((uint32_t)((kk * 2 + ahalf) ^ lxor)) << 4);
                    ldsm_x4(a[mt][0], a[mt][1], a[mt][2], a[mt][3], addr);
                }
#pragma unroll
                for (int bt = 0; bt < 2; bt++) {
                    const int row = wn * 32 + bt * 16 + lrow_b;
                    const uint32_t addr = bTile + row * 128 +
                        (((uint32_t)((kk * 2 + bhalf) ^ lxor)) << 4);
                    uint32_t r0, r1, r2, r3;
                    ldsm_x4(r0, r1, r2, r3, addr);
                    bfrag[2 * bt][0] = r0;     bfrag[2 * bt][1] = r1;
                    bfrag[2 * bt + 1][0] = r2; bfrag[2 * bt + 1][1] = r3;
                }
#pragma unroll
                for (int mt = 0; mt < 2; mt++)
#pragma unroll
                    for (int nt = 0; nt < 4; nt++)
                        mma16816(c[mt][nt], a[mt], bfrag[nt]);
            }
        }

        // stage MMA result into smem
        const int g  = lane >> 2;
        const int tg = lane & 3;
#pragma unroll
        for (int mt = 0; mt < 2; mt++) {
#pragma unroll
            for (int nt = 0; nt < 4; nt++) {
                const int col = wn * 32 + nt * 8 + tg * 2;
#pragma unroll
                for (int half = 0; half < 2; half++) {
                    const int row = wm * 32 + mt * 16 + g + half * 8;
                    gate_sm[row * GATE_W + col]     = c[mt][nt][half * 2 + 0];
                    gate_sm[row * GATE_W + col + 1] = c[mt][nt][half * 2 + 1];
                }
            }
        }
        __syncthreads();

        // cell math -> h registers + store to hcW (publish path first)
        float hreg[8];
#pragma unroll
        for (int jj = 0; jj < 8; jj++) {
            const int jloc = jh + jj;
            const int j = (nBase >> 2) + jloc;
            const float4 mm = *(const float4*)&gate_sm[bloc * GATE_W + jloc * 4];
            const float ig = sigf(mm.x + xr[jj].x);
            const float fg = sigf(mm.y + xr[jj].y);
            const float gg = tanhf(mm.z + xr[jj].z);
            const float og = sigf(mm.w + xr[jj].w);
            cc[jj] = fg * cc[jj] + ig * gg;
            hreg[jj] = og * tanhf(cc[jj]);
            const int chunk = j >> 6, col = j & 63;
            hcW[((size_t)chunk * BB + b) * 64 + col] = __float2half_rn(hreg[jj]);
        }

        // publish h, arrive at barrier EARLY
        __threadfence();
        __syncthreads();
        if (tid == 0) atomicAdd(&g_bar[mg], 1);

        // out-projection + final-state writes overlap peers' arrival
        float osum = 0.0f;
#pragma unroll
        for (int jj = 0; jj < 8; jj++) {
            osum += hreg[jj] * wout[jj];
            if (t == TT - 1) {
                hT[b * HH + j0 + jj] = hreg[jj];
                cT[b * HH + j0 + jj] = cc[jj];
            }
        }
        osum += __shfl_xor_sync(0xFFFFFFFFu, osum, 1);
        if ((tid & 1) == 0) atomicAdd(&out[t * BB + b], osum);

        // wait for the rest of the m-group
        if (tid == 0) {
            const int target = 64 * (t + 1);
            while (*barp < target) { __nanosleep(32); }
        }
        __syncthreads();
        __threadfence();
    }
}

// ===================== merged prep kernel ====================================
// blockIdx ranges: [0,65536) inputs | [65536,81920) W_ih | [81920,98304) W_hh
//                  [98304,100352) W1 | [100352,101376) setup
__global__ void prep_k(const float* __restrict__ inputs, const float* __restrict__ W1,
                       const float* __restrict__ W_ih, const float* __restrict__ W_hh,
                       const float* __restrict__ b_ih, const float* __restrict__ b_hh,
                       const float* __restrict__ h0,
                       float* __restrict__ out, const float* __restrict__ b_out)
{
    const int blk = blockIdx.x;
    const int tid = threadIdx.x;

    if (blk < 65536) {                       // inputs: R=32768, K=512, C=8
        const size_t i = (size_t)blk * 256 + tid;
        const int r = (int)(i >> 9);
        const int k = (int)(i & 511);
        const int chunk = k >> 6, col = k & 63;
        g_inc[((size_t)chunk * 32768 + r) * 64 + col] = __float2half_rn(inputs[i]);
    } else if (blk < 81920) {                // W_ih gate-perm
        const size_t i = (size_t)(blk - 65536) * 256 + tid;
        const int r = (int)(i >> 10);
        const int k = (int)(i & 1023);
        const int gt = r >> 10, j = r & 1023;
        const int rp = j * 4 + gt;
        const int chunk = k >> 6, col = k & 63;
        g_wihc[((size_t)chunk * 4096 + rp) * 64 + col] = __float2half_rn(W_ih[i]);
    } else if (blk < 98304) {                // W_hh gate-perm
        const size_t i = (size_t)(blk - 81920) * 256 + tid;
        const int r = (int)(i >> 10);
        const int k = (int)(i & 1023);
        const int gt = r >> 10, j = r & 1023;
        const int rp = j * 4 + gt;
        const int chunk = k >> 6, col = k & 63;
        g_whhc[((size_t)chunk * 4096 + rp) * 64 + col] = __float2half_rn(W_hh[i]);
    } else if (blk < 100352) {               // W1: R=1024, K=512
        const size_t i = (size_t)(blk - 98304) * 256 + tid;
        const int r = (int)(i >> 9);
        const int k = (int)(i & 511);
        const int chunk = k >> 6, col = k & 63;
        g_w1c[((size_t)chunk * 1024 + r) * 64 + col] = __float2half_rn(W1[i]);
    } else {                                 // setup: i in [0, B*H)
        const int i = (blk - 100352) * 256 + tid;
        if (i < 2) g_bar[i] = 0;
        if (i < GG) {
            const int gt = i & 3, j = i >> 2;
            const int s = gt * HH + j;
            g_bias[i] = b_ih[s] + b_hh[s];
        }
        if (i < TT * BB) out[i] = b_out[0];
        const int b = i >> 10, j = i & 1023;
        const int chunk = j >> 6, col = j & 63;
        g_hc[((size_t)chunk * BB + b) * 64 + col] = __float2half_rn(h0[i]);
    }
}

// ===================== launch ================================================
#define SMEM_BIG 98304

extern "C" void kernel_launch(void* const* d_in, const int* in_sizes, int n_in,
                              void* d_out, int out_size)
{
    const float* inputs = (const float*)d_in[0];
    const float* h0     = (const float*)d_in[1];
    const float* c0     = (const float*)d_in[2];
    const float* W1     = (const float*)d_in[3];
    const float* b1     = (const float*)d_in[4];
    const float* W_ih   = (const float*)d_in[5];
    const float* W_hh   = (const float*)d_in[6];
    const float* b_ih   = (const float*)d_in[7];
    const float* b_hh   = (const float*)d_in[8];
    const float* W_out  = (const float*)d_in[9];
    const float* b_out  = (const float*)d_in[10];

    float* out = (float*)d_out;
    float* hT  = out + TT * BB;
    float* cT  = hT + BB * HH;

    __half *pinc, *pxc, *pw1c, *pwihc, *pwhhc, *phc;
    float *pxg, *pbias;
    cudaGetSymbolAddress((void**)&pinc,  g_inc);
    cudaGetSymbolAddress((void**)&pxc,   g_xc);
    cudaGetSymbolAddress((void**)&pw1c,  g_w1c);
    cudaGetSymbolAddress((void**)&pwihc, g_wihc);
    cudaGetSymbolAddress((void**)&pwhhc, g_whhc);
    cudaGetSymbolAddress((void**)&phc,   g_hc);
    cudaGetSymbolAddress((void**)&pxg,   g_xg);
    cudaGetSymbolAddress((void**)&pbias, g_bias);

    cudaFuncSetAttribute((const void*)gemm_mma<0>, cudaFuncAttributeMaxDynamicSharedMemorySize, SMEM_BIG);
    cudaFuncSetAttribute((const void*)gemm_mma<1>, cudaFuncAttributeMaxDynamicSharedMemorySize, SMEM_BIG);
    cudaFuncSetAttribute((const void*)rec_persist_k, cudaFuncAttributeMaxDynamicSharedMemorySize, SMEM_REC);

    // single merged conversion + setup launch
    prep_k<<<101376, 256>>>(inputs, W1, W_ih, W_hh, b_ih, b_hh, h0, out, b_out);

    // GEMM1: x = relu(inputs @ W1^T + b1) -> hi store g_xc  (1-pass, C=8)
    {
        dim3 grid(HH / 128, 32768 / 128);
        gemm_mma<0><<<grid, 256, SMEM_BIG>>>(pinc, pw1c, b1, nullptr, pxc, 32768, HH, 8);
    }
    // GEMM2: xg' = x_hi @ W_ih_hi'^T + bias' -> g_xg  (1-pass, C=16)
    {
        dim3 grid(GG / 128, 32768 / 128);
        gemm_mma<1><<<grid, 256, SMEM_BIG>>>(pxc, pwihc, pbias, pxg, nullptr, 32768, GG, 16);
    }
    // persistent recurrence: 128 co-resident CTAs, smem-resident W, 4-deep pipe
    {
        dim3 grid(GG / 64, BB / 128);
        rec_persist_k<<<grid, 256, SMEM_REC>>>(phc, phc + HSPLIT, pwhhc, pxg,
                                               W_out, c0, out, hT, cT);
    }
}

// round 16
// speedup vs baseline: 1.5187x; 1.0399x over previous
#include <cuda_runtime.h>
#include <cuda_fp16.h>
#include <math.h>
#include <stdint.h>

#define TT 128
#define BB 256
#define DD 512
#define HH 1024
#define GG 4096   // 4*H

// ===================== scratch (static device globals) ======================
__device__ __align__(16) __half g_inc [(size_t)8  * 32768 * 64]; // inputs hi (C=8)
__device__ __align__(16) __half g_xc  [(size_t)16 * 32768 * 64]; // x hi      (C=16)
__device__ __align__(16) __half g_w1c [(size_t)8  * 1024  * 64]; // W1 hi
__device__ __align__(16) __half g_wihc[(size_t)16 * 4096  * 64]; // W_ih hi (gate-perm)
__device__ __align__(16) __half g_whhc[(size_t)16 * 4096  * 64]; // W_hh hi (gate-perm)
#define HSPLIT ((size_t)16 * 256 * 64)
__device__ __align__(16) __half g_hc  [2 * HSPLIT];              // h hi, ping-pong
__device__ __align__(16) __half g_xg[(size_t)TT * BB * GG];      // gate-perm cols, fp16 (256MB)
__device__ __align__(16) float g_bias[GG];                       // gate-perm
__device__ int g_bar[2];                                         // per-m-group step barrier

// ===================== PTX helpers ==========================================
__device__ __forceinline__ uint32_t smem_u32(const void* p) {
    return (uint32_t)__cvta_generic_to_shared(p);
}
__device__ __forceinline__ void cp_async16(uint32_t dst, const void* src) {
    asm volatile("cp.async.cg.shared.global [%0], [%1], 16;" :: "r"(dst), "l"(src));
}
__device__ __forceinline__ void cp_commit() {
    asm volatile("cp.async.commit_group;" ::: "memory");
}
template<int N>
__device__ __forceinline__ void cp_wait() {
    asm volatile("cp.async.wait_group %0;" :: "n"(N) : "memory");
}
__device__ __forceinline__ void ldsm_x4(uint32_t& r0, uint32_t& r1, uint32_t& r2, uint32_t& r3,
                                        uint32_t addr) {
    asm volatile("ldmatrix.sync.aligned.m8n8.x4.shared.b16 {%0,%1,%2,%3}, [%4];"
                 : "=r"(r0), "=r"(r1), "=r"(r2), "=r"(r3) : "r"(addr));
}
__device__ __forceinline__ void mma16816(float* c, const uint32_t* a, const uint32_t* b) {
    asm volatile(
        "mma.sync.aligned.m16n8k16.row.col.f32.f16.f16.f32 "
        "{%0,%1,%2,%3}, {%4,%5,%6,%7}, {%8,%9}, {%0,%1,%2,%3};"
        : "+f"(c[0]), "+f"(c[1]), "+f"(c[2]), "+f"(c[3])
        : "r"(a[0]), "r"(a[1]), "r"(a[2]), "r"(a[3]), "r"(b[0]), "r"(b[1]));
}

__device__ __forceinline__ void store_hi(__half* dst, int M, int m, int n, float v) {
    const int chunk = n >> 6, col = n & 63;
    dst[((size_t)chunk * M + m) * 64 + col] = __float2half_rn(v);
}

// chunk loader: A tile RA rows, B tile RB rows, 128B rows, XOR-swizzled
#define LOAD_CHUNK(A_, B_, M_, N_, mB_, nB_, RA_, RB_, ac_, bc_, dA_)             \
    do {                                                                          \
        const char* As_ = (const char*)((A_) + ((size_t)(ac_) * (M_) + (mB_)) * 64);\
        const char* Bs_ = (const char*)((B_) + ((size_t)(bc_) * (N_) + (nB_)) * 64);\
        const uint32_t dB_ = (dA_) + (RA_) * 128u;                                \
        _Pragma("unroll")                                                         \
        for (int q_ = 0; q_ < (RA_) / 32; q_++) {                                 \
            const int e_ = tid + q_ * 256;                                        \
            const int r_ = e_ >> 3, s_ = e_ & 7;                                  \
            const uint32_t off_ = r_ * 128 + (((uint32_t)(s_ ^ (r_ & 7))) << 4);  \
            cp_async16((dA_) + off_, As_ + r_ * 128 + s_ * 16);                   \
        }                                                                         \
        _Pragma("unroll")                                                         \
        for (int q_ = 0; q_ < (RB_) / 32; q_++) {                                 \
            const int e_ = tid + q_ * 256;                                        \
            const int r_ = e_ >> 3, s_ = e_ & 7;                                  \
            const uint32_t off_ = r_ * 128 + (((uint32_t)(s_ ^ (r_ & 7))) << 4);  \
            cp_async16(dB_ + off_, Bs_ + r_ * 128 + s_ * 16);                     \
        }                                                                         \
    } while (0)

// A-only loader (128 rows)
#define LOAD_A(A_, mB_, ac_, dA_)                                                 \
    do {                                                                          \
        const char* As_ = (const char*)((A_) + ((size_t)(ac_) * 256 + (mB_)) * 64);\
        _Pragma("unroll")                                                         \
        for (int q_ = 0; q_ < 4; q_++) {                                          \
            const int e_ = tid + q_ * 256;                                        \
            const int r_ = e_ >> 3, s_ = e_ & 7;                                  \
            const uint32_t off_ = r_ * 128 + (((uint32_t)(s_ ^ (r_ & 7))) << 4);  \
            cp_async16((dA_) + off_, As_ + r_ * 128 + s_ * 16);                   \
        }                                                                         \
    } while (0)

// ===================== big GEMMs (BM=BN=128, 3-stage single-sync, 2 CTA/SM) ==
// MODE 0: v=relu(v+aux[n]) -> hi store; MODE 1: v=v+aux[n] -> fp16 outH
template<int MODE>
__global__ __launch_bounds__(256, 2)
void gemm_mma(const __half* __restrict__ A, const __half* __restrict__ B,
              const float* __restrict__ aux, __half* __restrict__ outH,
              __half* __restrict__ outSplit, int M, int N, int C)
{
    extern __shared__ char smraw[];
    const uint32_t sbase = smem_u32(smraw);   // 3 stages x (A 16KB | B 16KB)

    const int tid  = threadIdx.x;
    const int lane = tid & 31;
    const int wid  = tid >> 5;
    const int wm   = wid & 3;
    const int wn   = wid >> 2;
    const int mBase = blockIdx.y * 128;
    const int nBase = blockIdx.x * 128;
    const int NIT = C;

    float c[2][8][4];
#pragma unroll
    for (int i = 0; i < 2; i++)
#pragma unroll
        for (int j = 0; j < 8; j++)
#pragma unroll
            for (int k = 0; k < 4; k++) c[i][j][k] = 0.0f;

    const int lrow_a = ((lane >> 3) & 1) * 8 + (lane & 7);
    const int lrow_b = (lane >> 4) * 8 + (lane & 7);
    const int lxor   = lane & 7;
    const int ahalf  = lane >> 4;
    const int bhalf  = (lane >> 3) & 1;

    LOAD_CHUNK(A, B, M, N, mBase, nBase, 128, 128, 0, 0, sbase);
    cp_commit();
    LOAD_CHUNK(A, B, M, N, mBase, nBase, 128, 128, 1, 1, sbase + 32768u);
    cp_commit();

    uint32_t curOff = 0u, nxtOff = 65536u;
    for (int i = 0; i < NIT; i++) {
        if (i == NIT - 1) cp_wait<0>(); else cp_wait<1>();
        __syncthreads();
        if (i + 2 < NIT) {
            LOAD_CHUNK(A, B, M, N, mBase, nBase, 128, 128, i + 2, i + 2, sbase + nxtOff);
            cp_commit();
        }

        const uint32_t aTile = sbase + curOff;
        const uint32_t bTile = aTile + 16384u;
        curOff = (curOff == 65536u) ? 0u : curOff + 32768u;
        nxtOff = (nxtOff == 65536u) ? 0u : nxtOff + 32768u;
#pragma unroll
        for (int kk = 0; kk < 4; kk++) {
            uint32_t a[2][4], b[8][2];
#pragma unroll
            for (int mt = 0; mt < 2; mt++) {
                const int row = wm * 32 + mt * 16 + lrow_a;
                const uint32_t addr = aTile + row * 128 +
                    (((uint32_t)((kk * 2 + ahalf) ^ lxor)) << 4);
                ldsm_x4(a[mt][0], a[mt][1], a[mt][2], a[mt][3], addr);
            }
#pragma unroll
            for (int bt = 0; bt < 4; bt++) {
                const int row = wn * 64 + bt * 16 + lrow_b;
                const uint32_t addr = bTile + row * 128 +
                    (((uint32_t)((kk * 2 + bhalf) ^ lxor)) << 4);
                uint32_t r0, r1, r2, r3;
                ldsm_x4(r0, r1, r2, r3, addr);
                b[2 * bt][0] = r0;     b[2 * bt][1] = r1;
                b[2 * bt + 1][0] = r2; b[2 * bt + 1][1] = r3;
            }
#pragma unroll
            for (int mt = 0; mt < 2; mt++)
#pragma unroll
                for (int nt = 0; nt < 8; nt++)
                    mma16816(c[mt][nt], a[mt], b[nt]);
        }
    }

    const int g  = lane >> 2;
    const int tg = lane & 3;
#pragma unroll
    for (int mt = 0; mt < 2; mt++) {
        const int m0 = mBase + wm * 32 + mt * 16 + g;
#pragma unroll
        for (int nt = 0; nt < 8; nt++) {
            const int n0 = nBase + wn * 64 + nt * 8 + tg * 2;
#pragma unroll
            for (int half = 0; half < 2; half++) {
                const int m = m0 + half * 8;
                const float v0 = c[mt][nt][half * 2 + 0];
                const float v1 = c[mt][nt][half * 2 + 1];
                if (MODE == 0) {
                    store_hi(outSplit, M, m, n0,     fmaxf(v0 + aux[n0],     0.0f));
                    store_hi(outSplit, M, m, n0 + 1, fmaxf(v1 + aux[n0 + 1], 0.0f));
                } else {
                    __half2 hv = __floats2half2_rn(v0 + aux[n0], v1 + aux[n0 + 1]);
                    *(__half2*)(outH + (size_t)m * N + n0) = hv;
                }
            }
        }
    }
}

// ===================== persistent fused recurrence ===========================
// W_hh in smem; 4-deep A pipeline, one sync/iter; per-m-group barrier;
// epilogue: h publish + barrier arrive BEFORE out-projection. xg in fp16.
#define GATE_W 68
#define SM_W    0u
#define SM_A    131072u
#define SM_GATE 196608u
#define SMEM_REC (196608 + 128 * GATE_W * 4)

__device__ __forceinline__ float sigf(float x) { return 1.0f / (1.0f + __expf(-x)); }

__global__ __launch_bounds__(256, 1)
void rec_persist_k(__half* __restrict__ hc0, __half* __restrict__ hc1,
                   const __half* __restrict__ whh, const __half* __restrict__ xg,
                   const float* __restrict__ W_out, const float* __restrict__ c0,
                   float* __restrict__ out, float* __restrict__ hT, float* __restrict__ cT)
{
    extern __shared__ char smraw[];
    const uint32_t sbase = smem_u32(smraw);
    float* gate_sm = (float*)(smraw + SM_GATE);

    const int tid  = threadIdx.x;
    const int lane = tid & 31;
    const int wid  = tid >> 5;
    const int wm   = wid & 3;
    const int wn   = wid >> 2;
    const int nBase = blockIdx.x * 64;
    const int mBase = blockIdx.y * 128;
    const int mg    = blockIdx.y;

    const int lrow_a = ((lane >> 3) & 1) * 8 + (lane & 7);
    const int lrow_b = (lane >> 4) * 8 + (lane & 7);
    const int lxor   = lane & 7;
    const int ahalf  = lane >> 4;
    const int bhalf  = (lane >> 3) & 1;

    // one-time W_hh preload
#pragma unroll
    for (int c = 0; c < 16; c++) {
        const char* Bs = (const char*)(whh + ((size_t)c * 4096 + nBase) * 64);
#pragma unroll
        for (int q = 0; q < 2; q++) {
            const int e = tid + q * 256;
            const int r = e >> 3, s = e & 7;
            const uint32_t off = r * 128 + (((uint32_t)(s ^ (r & 7))) << 4);
            cp_async16(sbase + SM_W + c * 8192u + off, Bs + r * 128 + s * 16);
        }
    }
    cp_commit();

    const int bloc = tid >> 1;
    const int b = mBase + bloc;
    const int jh = (tid & 1) * 8;
    const int j0 = (nBase >> 2) + jh;
    float cc[8], wout[8];
#pragma unroll
    for (int jj = 0; jj < 8; jj++) {
        cc[jj]   = c0[b * HH + j0 + jj];
        wout[jj] = W_out[j0 + jj];
    }

    volatile int* barp = &g_bar[mg];
    cp_wait<0>();
    __syncthreads();

    for (int t = 0; t < TT; t++) {
        const __half* hcR = (t & 1) ? hc1 : hc0;
        __half*       hcW = (t & 1) ? hc0 : hc1;
        const __half* xg_t = xg + (size_t)t * BB * GG;

        // prefetch this thread's xg slice (32 consecutive halves, 64B aligned)
        const __half2* xp = (const __half2*)(xg_t + (size_t)b * GG + nBase + jh * 4);
        __half2 xh[16];
#pragma unroll
        for (int q = 0; q < 16; q++) xh[q] = xp[q];

        float c[2][4][4];
#pragma unroll
        for (int i = 0; i < 2; i++)
#pragma unroll
            for (int j = 0; j < 4; j++)
#pragma unroll
                for (int k = 0; k < 4; k++) c[i][j][k] = 0.0f;

#pragma unroll
        for (int p = 0; p < 3; p++) {
            LOAD_A(hcR, mBase, p, sbase + SM_A + (uint32_t)p * 16384u);
            cp_commit();
        }

        for (int i = 0; i < 16; i++) {
            if (i <= 13)      cp_wait<2>();
            else if (i == 14) cp_wait<1>();
            else              cp_wait<0>();
            __syncthreads();
            if (i + 3 < 16) {
                LOAD_A(hcR, mBase, i + 3, sbase + SM_A + (uint32_t)((i + 3) & 3) * 16384u);
                cp_commit();
            }

            const uint32_t aTile = sbase + SM_A + (uint32_t)(i & 3) * 16384u;
            const uint32_t bTile = sbase + SM_W + (uint32_t)i * 8192u;
#pragma unroll
            for (int kk = 0; kk < 4; kk++) {
                uint32_t a[2][4], bfrag[4][2];
#pragma unroll
                for (int mt = 0; mt < 2; mt++) {
                    const int row = wm * 32 + mt * 16 + lrow_a;
                    const uint32_t addr = aTile + row * 128 +
                        (((uint32_t)((kk * 2 + ahalf) ^ lxor)) << 4);
                    ldsm_x4(a[mt][0], a[mt][1], a[mt][2], a[mt][3], addr);
                }
#pragma unroll
                for (int bt = 0; bt < 2; bt++) {
                    const int row = wn * 32 + bt * 16 + lrow_b;
                    const uint32_t addr = bTile + row * 128 +
                        (((uint32_t)((kk * 2 + bhalf) ^ lxor)) << 4);
                    uint32_t r0, r1, r2, r3;
                    ldsm_x4(r0, r1, r2, r3, addr);
                    bfrag[2 * bt][0] = r0;     bfrag[2 * bt][1] = r1;
                    bfrag[2 * bt + 1][0] = r2; bfrag[2 * bt + 1][1] = r3;
                }
#pragma unroll
                for (int mt = 0; mt < 2; mt++)
#pragma unroll
                    for (int nt = 0; nt < 4; nt++)
                        mma16816(c[mt][nt], a[mt], bfrag[nt]);
            }
        }

        // stage MMA result into smem
        const int g  = lane >> 2;
        const int tg = lane & 3;
#pragma unroll
        for (int mt = 0; mt < 2; mt++) {
#pragma unroll
            for (int nt = 0; nt < 4; nt++) {
                const int col = wn * 32 + nt * 8 + tg * 2;
#pragma unroll
                for (int half = 0; half < 2; half++) {
                    const int row = wm * 32 + mt * 16 + g + half * 8;
                    gate_sm[row * GATE_W + col]     = c[mt][nt][half * 2 + 0];
                    gate_sm[row * GATE_W + col + 1] = c[mt][nt][half * 2 + 1];
                }
            }
        }
        __syncthreads();

        // cell math -> h registers + store to hcW (publish path first)
        float hreg[8];
#pragma unroll
        for (int jj = 0; jj < 8; jj++) {
            const int jloc = jh + jj;
            const int j = (nBase >> 2) + jloc;
            const float4 mm = *(const float4*)&gate_sm[bloc * GATE_W + jloc * 4];
            const float2 x01 = __half22float2(xh[2 * jj]);
            const float2 x23 = __half22float2(xh[2 * jj + 1]);
            const float ig = sigf(mm.x + x01.x);
            const float fg = sigf(mm.y + x01.y);
            const float gg = tanhf(mm.z + x23.x);
            const float og = sigf(mm.w + x23.y);
            cc[jj] = fg * cc[jj] + ig * gg;
            hreg[jj] = og * tanhf(cc[jj]);
            const int chunk = j >> 6, col = j & 63;
            hcW[((size_t)chunk * BB + b) * 64 + col] = __float2half_rn(hreg[jj]);
        }

        // publish h, arrive at barrier EARLY
        __threadfence();
        __syncthreads();
        if (tid == 0) atomicAdd(&g_bar[mg], 1);

        // out-projection + final-state writes overlap peers' arrival
        float osum = 0.0f;
#pragma unroll
        for (int jj = 0; jj < 8; jj++) {
            osum += hreg[jj] * wout[jj];
            if (t == TT - 1) {
                hT[b * HH + j0 + jj] = hreg[jj];
                cT[b * HH + j0 + jj] = cc[jj];
            }
        }
        osum += __shfl_xor_sync(0xFFFFFFFFu, osum, 1);
        if ((tid & 1) == 0) atomicAdd(&out[t * BB + b], osum);

        if (tid == 0) {
            const int target = 64 * (t + 1);
            while (*barp < target) { __nanosleep(32); }
        }
        __syncthreads();
        __threadfence();
    }
}

// ===================== merged prep kernel ====================================
// blockIdx ranges: [0,65536) inputs | [65536,81920) W_ih | [81920,98304) W_hh
//                  [98304,100352) W1 | [100352,101376) setup
__global__ void prep_k(const float* __restrict__ inputs, const float* __restrict__ W1,
                       const float* __restrict__ W_ih, const float* __restrict__ W_hh,
                       const float* __restrict__ b_ih, const float* __restrict__ b_hh,
                       const float* __restrict__ h0,
                       float* __restrict__ out, const float* __restrict__ b_out)
{
    const int blk = blockIdx.x;
    const int tid = threadIdx.x;

    if (blk < 65536) {                       // inputs: R=32768, K=512, C=8
        const size_t i = (size_t)blk * 256 + tid;
        const int r = (int)(i >> 9);
        const int k = (int)(i & 511);
        const int chunk = k >> 6, col = k & 63;
        g_inc[((size_t)chunk * 32768 + r) * 64 + col] = __float2half_rn(inputs[i]);
    } else if (blk < 81920) {                // W_ih gate-perm
        const size_t i = (size_t)(blk - 65536) * 256 + tid;
        const int r = (int)(i >> 10);
        const int k = (int)(i & 1023);
        const int gt = r >> 10, j = r & 1023;
        const int rp = j * 4 + gt;
        const int chunk = k >> 6, col = k & 63;
        g_wihc[((size_t)chunk * 4096 + rp) * 64 + col] = __float2half_rn(W_ih[i]);
    } else if (blk < 98304) {                // W_hh gate-perm
        const size_t i = (size_t)(blk - 81920) * 256 + tid;
        const int r = (int)(i >> 10);
        const int k = (int)(i & 1023);
        const int gt = r >> 10, j = r & 1023;
        const int rp = j * 4 + gt;
        const int chunk = k >> 6, col = k & 63;
        g_whhc[((size_t)chunk * 4096 + rp) * 64 + col] = __float2half_rn(W_hh[i]);
    } else if (blk < 100352) {               // W1: R=1024, K=512
        const size_t i = (size_t)(blk - 98304) * 256 + tid;
        const int r = (int)(i >> 9);
        const int k = (int)(i & 511);
        const int chunk = k >> 6, col = k & 63;
        g_w1c[((size_t)chunk * 1024 + r) * 64 + col] = __float2half_rn(W1[i]);
    } else {                                 // setup: i in [0, B*H)
        const int i = (blk - 100352) * 256 + tid;
        if (i < 2) g_bar[i] = 0;
        if (i < GG) {
            const int gt = i & 3, j = i >> 2;
            const int s = gt * HH + j;
            g_bias[i] = b_ih[s] + b_hh[s];
        }
        if (i < TT * BB) out[i] = b_out[0];
        const int b = i >> 10, j = i & 1023;
        const int chunk = j >> 6, col = j & 63;
        g_hc[((size_t)chunk * BB + b) * 64 + col] = __float2half_rn(h0[i]);
    }
}

// ===================== launch ================================================
#define SMEM_BIG 98304

extern "C" void kernel_launch(void* const* d_in, const int* in_sizes, int n_in,
                              void* d_out, int out_size)
{
    const float* inputs = (const float*)d_in[0];
    const float* h0     = (const float*)d_in[1];
    const float* c0     = (const float*)d_in[2];
    const float* W1     = (const float*)d_in[3];
    const float* b1     = (const float*)d_in[4];
    const float* W_ih   = (const float*)d_in[5];
    const float* W_hh   = (const float*)d_in[6];
    const float* b_ih   = (const float*)d_in[7];
    const float* b_hh   = (const float*)d_in[8];
    const float* W_out  = (const float*)d_in[9];
    const float* b_out  = (const float*)d_in[10];

    float* out = (float*)d_out;
    float* hT  = out + TT * BB;
    float* cT  = hT + BB * HH;

    __half *pinc, *pxc, *pw1c, *pwihc, *pwhhc, *phc, *pxg;
    float *pbias;
    cudaGetSymbolAddress((void**)&pinc,  g_inc);
    cudaGetSymbolAddress((void**)&pxc,   g_xc);
    cudaGetSymbolAddress((void**)&pw1c,  g_w1c);
    cudaGetSymbolAddress((void**)&pwihc, g_wihc);
    cudaGetSymbolAddress((void**)&pwhhc, g_whhc);
    cudaGetSymbolAddress((void**)&phc,   g_hc);
    cudaGetSymbolAddress((void**)&pxg,   g_xg);
    cudaGetSymbolAddress((void**)&pbias, g_bias);

    cudaFuncSetAttribute((const void*)gemm_mma<0>, cudaFuncAttributeMaxDynamicSharedMemorySize, SMEM_BIG);
    cudaFuncSetAttribute((const void*)gemm_mma<1>, cudaFuncAttributeMaxDynamicSharedMemorySize, SMEM_BIG);
    cudaFuncSetAttribute((const void*)rec_persist_k, cudaFuncAttributeMaxDynamicSharedMemorySize, SMEM_REC);

    // single merged conversion + setup launch
    prep_k<<<101376, 256>>>(inputs, W1, W_ih, W_hh, b_ih, b_hh, h0, out, b_out);

    // GEMM1: x = relu(inputs @ W1^T + b1) -> hi store g_xc  (1-pass, C=8)
    {
        dim3 grid(HH / 128, 32768 / 128);
        gemm_mma<0><<<grid, 256, SMEM_BIG>>>(pinc, pw1c, b1, nullptr, pxc, 32768, HH, 8);
    }
    // GEMM2: xg' = x_hi @ W_ih_hi'^T + bias' -> g_xg (fp16)  (1-pass, C=16)
    {
        dim3 grid(GG / 128, 32768 / 128);
        gemm_mma<1><<<grid, 256, SMEM_BIG>>>(pxc, pwihc, pbias, pxg, nullptr, 32768, GG, 16);
    }
    // persistent recurrence: 128 co-resident CTAs, smem-resident W, 4-deep pipe
    {
        dim3 grid(GG / 64, BB / 128);
        rec_persist_k<<<grid, 256, SMEM_REC>>>(phc, phc + HSPLIT, pwhhc, pxg,
                                               W_out, c0, out, hT, cT);
    }
}

// round 17
// speedup vs baseline: 1.5472x; 1.0188x over previous
#include <cuda_runtime.h>
#include <cuda_fp16.h>
#include <math.h>
#include <stdint.h>

#define TT 128
#define BB 256
#define DD 512
#define HH 1024
#define GG 4096   // 4*H

// ===================== scratch (static device globals) ======================
__device__ __align__(16) __half g_inc [(size_t)8  * 32768 * 64]; // inputs hi (C=8)
__device__ __align__(16) __half g_xc  [(size_t)16 * 32768 * 64]; // x hi      (C=16)
__device__ __align__(16) __half g_w1c [(size_t)8  * 1024  * 64]; // W1 hi
__device__ __align__(16) __half g_wihc[(size_t)16 * 4096  * 64]; // W_ih hi (gate-perm)
__device__ __align__(16) __half g_whhc[(size_t)16 * 4096  * 64]; // W_hh hi (gate-perm)
#define HSPLIT ((size_t)16 * 256 * 64)
__device__ __align__(16) __half g_hc  [2 * HSPLIT];              // h hi, ping-pong
__device__ __align__(16) __half g_xg[(size_t)TT * BB * GG];      // gate-perm cols, fp16
__device__ __align__(16) float g_bias[GG];                       // gate-perm
__device__ int g_bar[2];                                         // per-m-group step barrier

// ===================== PTX helpers ==========================================
__device__ __forceinline__ uint32_t smem_u32(const void* p) {
    return (uint32_t)__cvta_generic_to_shared(p);
}
__device__ __forceinline__ void cp_async16(uint32_t dst, const void* src) {
    asm volatile("cp.async.cg.shared.global [%0], [%1], 16;" :: "r"(dst), "l"(src));
}
__device__ __forceinline__ void cp_commit() {
    asm volatile("cp.async.commit_group;" ::: "memory");
}
template<int N>
__device__ __forceinline__ void cp_wait() {
    asm volatile("cp.async.wait_group %0;" :: "n"(N) : "memory");
}
__device__ __forceinline__ void ldsm_x4(uint32_t& r0, uint32_t& r1, uint32_t& r2, uint32_t& r3,
                                        uint32_t addr) {
    asm volatile("ldmatrix.sync.aligned.m8n8.x4.shared.b16 {%0,%1,%2,%3}, [%4];"
                 : "=r"(r0), "=r"(r1), "=r"(r2), "=r"(r3) : "r"(addr));
}
__device__ __forceinline__ void mma16816(float* c, const uint32_t* a, const uint32_t* b) {
    asm volatile(
        "mma.sync.aligned.m16n8k16.row.col.f32.f16.f16.f32 "
        "{%0,%1,%2,%3}, {%4,%5,%6,%7}, {%8,%9}, {%0,%1,%2,%3};"
        : "+f"(c[0]), "+f"(c[1]), "+f"(c[2]), "+f"(c[3])
        : "r"(a[0]), "r"(a[1]), "r"(a[2]), "r"(a[3]), "r"(b[0]), "r"(b[1]));
}

__device__ __forceinline__ void store_hi(__half* dst, int M, int m, int n, float v) {
    const int chunk = n >> 6, col = n & 63;
    dst[((size_t)chunk * M + m) * 64 + col] = __float2half_rn(v);
}

// chunk loader: A tile RA rows, B tile RB rows, 128B rows, XOR-swizzled
#define LOAD_CHUNK(A_, B_, M_, N_, mB_, nB_, RA_, RB_, ac_, bc_, dA_)             \
    do {                                                                          \
        const char* As_ = (const char*)((A_) + ((size_t)(ac_) * (M_) + (mB_)) * 64);\
        const char* Bs_ = (const char*)((B_) + ((size_t)(bc_) * (N_) + (nB_)) * 64);\
        const uint32_t dB_ = (dA_) + (RA_) * 128u;                                \
        _Pragma("unroll")                                                         \
        for (int q_ = 0; q_ < (RA_) / 32; q_++) {                                 \
            const int e_ = tid + q_ * 256;                                        \
            const int r_ = e_ >> 3, s_ = e_ & 7;                                  \
            const uint32_t off_ = r_ * 128 + (((uint32_t)(s_ ^ (r_ & 7))) << 4);  \
            cp_async16((dA_) + off_, As_ + r_ * 128 + s_ * 16);                   \
        }                                                                         \
        _Pragma("unroll")                                                         \
        for (int q_ = 0; q_ < (RB_) / 32; q_++) {                                 \
            const int e_ = tid + q_ * 256;                                        \
            const int r_ = e_ >> 3, s_ = e_ & 7;                                  \
            const uint32_t off_ = r_ * 128 + (((uint32_t)(s_ ^ (r_ & 7))) << 4);  \
            cp_async16(dB_ + off_, Bs_ + r_ * 128 + s_ * 16);                     \
        }                                                                         \
    } while (0)

// A-only loader (128 rows)
#define LOAD_A(A_, mB_, ac_, dA_)                                                 \
    do {                                                                          \
        const char* As_ = (const char*)((A_) + ((size_t)(ac_) * 256 + (mB_)) * 64);\
        _Pragma("unroll")                                                         \
        for (int q_ = 0; q_ < 4; q_++) {                                          \
            const int e_ = tid + q_ * 256;                                        \
            const int r_ = e_ >> 3, s_ = e_ & 7;                                  \
            const uint32_t off_ = r_ * 128 + (((uint32_t)(s_ ^ (r_ & 7))) << 4);  \
            cp_async16((dA_) + off_, As_ + r_ * 128 + s_ * 16);                   \
        }                                                                         \
    } while (0)

// ===================== big GEMMs (BM=BN=128, 3-stage single-sync, 2 CTA/SM) ==
// MODE 0: v=relu(v+aux[n]) -> hi store; MODE 1: v=v+aux[n] -> fp16 outH (stream)
template<int MODE>
__global__ __launch_bounds__(256, 2)
void gemm_mma(const __half* __restrict__ A, const __half* __restrict__ B,
              const float* __restrict__ aux, __half* __restrict__ outH,
              __half* __restrict__ outSplit, int M, int N, int C)
{
    extern __shared__ char smraw[];
    const uint32_t sbase = smem_u32(smraw);   // 3 stages x (A 16KB | B 16KB)

    const int tid  = threadIdx.x;
    const int lane = tid & 31;
    const int wid  = tid >> 5;
    const int wm   = wid & 3;
    const int wn   = wid >> 2;
    const int mBase = blockIdx.y * 128;
    const int nBase = blockIdx.x * 128;
    const int NIT = C;

    float c[2][8][4];
#pragma unroll
    for (int i = 0; i < 2; i++)
#pragma unroll
        for (int j = 0; j < 8; j++)
#pragma unroll
            for (int k = 0; k < 4; k++) c[i][j][k] = 0.0f;

    const int lrow_a = ((lane >> 3) & 1) * 8 + (lane & 7);
    const int lrow_b = (lane >> 4) * 8 + (lane & 7);
    const int lxor   = lane & 7;
    const int ahalf  = lane >> 4;
    const int bhalf  = (lane >> 3) & 1;

    LOAD_CHUNK(A, B, M, N, mBase, nBase, 128, 128, 0, 0, sbase);
    cp_commit();
    LOAD_CHUNK(A, B, M, N, mBase, nBase, 128, 128, 1, 1, sbase + 32768u);
    cp_commit();

    uint32_t curOff = 0u, nxtOff = 65536u;
    for (int i = 0; i < NIT; i++) {
        if (i == NIT - 1) cp_wait<0>(); else cp_wait<1>();
        __syncthreads();
        if (i + 2 < NIT) {
            LOAD_CHUNK(A, B, M, N, mBase, nBase, 128, 128, i + 2, i + 2, sbase + nxtOff);
            cp_commit();
        }

        const uint32_t aTile = sbase + curOff;
        const uint32_t bTile = aTile + 16384u;
        curOff = (curOff == 65536u) ? 0u : curOff + 32768u;
        nxtOff = (nxtOff == 65536u) ? 0u : nxtOff + 32768u;
#pragma unroll
        for (int kk = 0; kk < 4; kk++) {
            uint32_t a[2][4], b[8][2];
#pragma unroll
            for (int mt = 0; mt < 2; mt++) {
                const int row = wm * 32 + mt * 16 + lrow_a;
                const uint32_t addr = aTile + row * 128 +
                    (((uint32_t)((kk * 2 + ahalf) ^ lxor)) << 4);
                ldsm_x4(a[mt][0], a[mt][1], a[mt][2], a[mt][3], addr);
            }
#pragma unroll
            for (int bt = 0; bt < 4; bt++) {
                const int row = wn * 64 + bt * 16 + lrow_b;
                const uint32_t addr = bTile + row * 128 +
                    (((uint32_t)((kk * 2 + bhalf) ^ lxor)) << 4);
                uint32_t r0, r1, r2, r3;
                ldsm_x4(r0, r1, r2, r3, addr);
                b[2 * bt][0] = r0;     b[2 * bt][1] = r1;
                b[2 * bt + 1][0] = r2; b[2 * bt + 1][1] = r3;
            }
#pragma unroll
            for (int mt = 0; mt < 2; mt++)
#pragma unroll
                for (int nt = 0; nt < 8; nt++)
                    mma16816(c[mt][nt], a[mt], b[nt]);
        }
    }

    const int g  = lane >> 2;
    const int tg = lane & 3;
#pragma unroll
    for (int mt = 0; mt < 2; mt++) {
        const int m0 = mBase + wm * 32 + mt * 16 + g;
#pragma unroll
        for (int nt = 0; nt < 8; nt++) {
            const int n0 = nBase + wn * 64 + nt * 8 + tg * 2;
#pragma unroll
            for (int half = 0; half < 2; half++) {
                const int m = m0 + half * 8;
                const float v0 = c[mt][nt][half * 2 + 0];
                const float v1 = c[mt][nt][half * 2 + 1];
                if (MODE == 0) {
                    store_hi(outSplit, M, m, n0,     fmaxf(v0 + aux[n0],     0.0f));
                    store_hi(outSplit, M, m, n0 + 1, fmaxf(v1 + aux[n0 + 1], 0.0f));
                } else {
                    __half2 hv = __floats2half2_rn(v0 + aux[n0], v1 + aux[n0 + 1]);
                    __stcs((__half2*)(outH + (size_t)m * N + n0), hv);
                }
            }
        }
    }
}

// ===================== persistent fused recurrence ===========================
// W_hh in smem; 4-deep A pipeline, one sync/iter; per-m-group barrier;
// epilogue: h publish + barrier arrive BEFORE out-projection. xg fp16 streaming.
#define GATE_W 68
#define SM_W    0u
#define SM_A    131072u
#define SM_GATE 196608u
#define SMEM_REC (196608 + 128 * GATE_W * 4)

__device__ __forceinline__ float sigf(float x) { return 1.0f / (1.0f + __expf(-x)); }

__global__ __launch_bounds__(256, 1)
void rec_persist_k(__half* __restrict__ hc0, __half* __restrict__ hc1,
                   const __half* __restrict__ whh, const __half* __restrict__ xg,
                   const float* __restrict__ W_out, const float* __restrict__ c0,
                   float* __restrict__ out, float* __restrict__ hT, float* __restrict__ cT)
{
    extern __shared__ char smraw[];
    const uint32_t sbase = smem_u32(smraw);
    float* gate_sm = (float*)(smraw + SM_GATE);

    const int tid  = threadIdx.x;
    const int lane = tid & 31;
    const int wid  = tid >> 5;
    const int wm   = wid & 3;
    const int wn   = wid >> 2;
    const int nBase = blockIdx.x * 64;
    const int mBase = blockIdx.y * 128;
    const int mg    = blockIdx.y;

    const int lrow_a = ((lane >> 3) & 1) * 8 + (lane & 7);
    const int lrow_b = (lane >> 4) * 8 + (lane & 7);
    const int lxor   = lane & 7;
    const int ahalf  = lane >> 4;
    const int bhalf  = (lane >> 3) & 1;

    // one-time W_hh preload
#pragma unroll
    for (int c = 0; c < 16; c++) {
        const char* Bs = (const char*)(whh + ((size_t)c * 4096 + nBase) * 64);
#pragma unroll
        for (int q = 0; q < 2; q++) {
            const int e = tid + q * 256;
            const int r = e >> 3, s = e & 7;
            const uint32_t off = r * 128 + (((uint32_t)(s ^ (r & 7))) << 4);
            cp_async16(sbase + SM_W + c * 8192u + off, Bs + r * 128 + s * 16);
        }
    }
    cp_commit();

    const int bloc = tid >> 1;
    const int b = mBase + bloc;
    const int jh = (tid & 1) * 8;
    const int j0 = (nBase >> 2) + jh;
    float cc[8], wout[8];
#pragma unroll
    for (int jj = 0; jj < 8; jj++) {
        cc[jj]   = c0[b * HH + j0 + jj];
        wout[jj] = W_out[j0 + jj];
    }

    volatile int* barp = &g_bar[mg];
    cp_wait<0>();
    __syncthreads();

    for (int t = 0; t < TT; t++) {
        const __half* hcR = (t & 1) ? hc1 : hc0;
        __half*       hcW = (t & 1) ? hc0 : hc1;
        const __half* xg_t = xg + (size_t)t * BB * GG;

        // prefetch this thread's xg slice (streaming: read-once data)
        const __half2* xp = (const __half2*)(xg_t + (size_t)b * GG + nBase + jh * 4);
        __half2 xh[16];
#pragma unroll
        for (int q = 0; q < 16; q++) xh[q] = __ldcs(xp + q);

        float c[2][4][4];
#pragma unroll
        for (int i = 0; i < 2; i++)
#pragma unroll
            for (int j = 0; j < 4; j++)
#pragma unroll
                for (int k = 0; k < 4; k++) c[i][j][k] = 0.0f;

#pragma unroll
        for (int p = 0; p < 3; p++) {
            LOAD_A(hcR, mBase, p, sbase + SM_A + (uint32_t)p * 16384u);
            cp_commit();
        }

        for (int i = 0; i < 16; i++) {
            if (i <= 13)      cp_wait<2>();
            else if (i == 14) cp_wait<1>();
            else              cp_wait<0>();
            __syncthreads();
            if (i + 3 < 16) {
                LOAD_A(hcR, mBase, i + 3, sbase + SM_A + (uint32_t)((i + 3) & 3) * 16384u);
                cp_commit();
            }

            const uint32_t aTile = sbase + SM_A + (uint32_t)(i & 3) * 16384u;
            const uint32_t bTile = sbase + SM_W + (uint32_t)i * 8192u;
#pragma unroll
            for (int kk = 0; kk < 4; kk++) {
                uint32_t a[2][4], bfrag[4][2];
#pragma unroll
                for (int mt = 0; mt < 2; mt++) {
                    const int row = wm * 32 + mt * 16 + lrow_a;
                    const uint32_t addr = aTile + row * 128 +
                        (((uint32_t)((kk * 2 + ahalf) ^ lxor)) << 4);
                    ldsm_x4(a[mt][0], a[mt][1], a[mt][2], a[mt][3], addr);
                }
#pragma unroll
                for (int bt = 0; bt < 2; bt++) {
                    const int row = wn * 32 + bt * 16 + lrow_b;
                    const uint32_t addr = bTile + row * 128 +
                        (((uint32_t)((kk * 2 + bhalf) ^ lxor)) << 4);
                    uint32_t r0, r1, r2, r3;
                    ldsm_x4(r0, r1, r2, r3, addr);
                    bfrag[2 * bt][0] = r0;     bfrag[2 * bt][1] = r1;
                    bfrag[2 * bt + 1][0] = r2; bfrag[2 * bt + 1][1] = r3;
                }
#pragma unroll
                for (int mt = 0; mt < 2; mt++)
#pragma unroll
                    for (int nt = 0; nt < 4; nt++)
                        mma16816(c[mt][nt], a[mt], bfrag[nt]);
            }
        }

        // stage MMA result into smem
        const int g  = lane >> 2;
        const int tg = lane & 3;
#pragma unroll
        for (int mt = 0; mt < 2; mt++) {
#pragma unroll
            for (int nt = 0; nt < 4; nt++) {
                const int col = wn * 32 + nt * 8 + tg * 2;
#pragma unroll
                for (int half = 0; half < 2; half++) {
                    const int row = wm * 32 + mt * 16 + g + half * 8;
                    gate_sm[row * GATE_W + col]     = c[mt][nt][half * 2 + 0];
                    gate_sm[row * GATE_W + col + 1] = c[mt][nt][half * 2 + 1];
                }
            }
        }
        __syncthreads();

        // cell math -> h registers + store to hcW (publish path first)
        float hreg[8];
#pragma unroll
        for (int jj = 0; jj < 8; jj++) {
            const int jloc = jh + jj;
            const int j = (nBase >> 2) + jloc;
            const float4 mm = *(const float4*)&gate_sm[bloc * GATE_W + jloc * 4];
            const float2 x01 = __half22float2(xh[2 * jj]);
            const float2 x23 = __half22float2(xh[2 * jj + 1]);
            const float ig = sigf(mm.x + x01.x);
            const float fg = sigf(mm.y + x01.y);
            const float gg = tanhf(mm.z + x23.x);
            const float og = sigf(mm.w + x23.y);
            cc[jj] = fg * cc[jj] + ig * gg;
            hreg[jj] = og * tanhf(cc[jj]);
            const int chunk = j >> 6, col = j & 63;
            hcW[((size_t)chunk * BB + b) * 64 + col] = __float2half_rn(hreg[jj]);
        }

        // publish h, arrive at barrier EARLY
        __threadfence();
        __syncthreads();
        if (tid == 0) atomicAdd(&g_bar[mg], 1);

        // out-projection + final-state writes overlap peers' arrival
        float osum = 0.0f;
#pragma unroll
        for (int jj = 0; jj < 8; jj++) {
            osum += hreg[jj] * wout[jj];
            if (t == TT - 1) {
                hT[b * HH + j0 + jj] = hreg[jj];
                cT[b * HH + j0 + jj] = cc[jj];
            }
        }
        osum += __shfl_xor_sync(0xFFFFFFFFu, osum, 1);
        if ((tid & 1) == 0) atomicAdd(&out[t * BB + b], osum);

        if (tid == 0) {
            const int target = 64 * (t + 1);
            while (*barp < target) { __nanosleep(32); }
        }
        __syncthreads();
        __threadfence();
    }
}

// ===================== merged prep kernel (vectorized x4) =====================
// blockIdx ranges (4 elems/thread): [0,16384) inputs | [16384,20480) W_ih
//   [20480,24576) W_hh | [24576,25088) W1 | [25088,26112) setup (scalar)
__global__ void prep_k(const float* __restrict__ inputs, const float* __restrict__ W1,
                       const float* __restrict__ W_ih, const float* __restrict__ W_hh,
                       const float* __restrict__ b_ih, const float* __restrict__ b_hh,
                       const float* __restrict__ h0,
                       float* __restrict__ out, const float* __restrict__ b_out)
{
    const int blk = blockIdx.x;
    const int tid = threadIdx.x;

    if (blk < 16384) {                       // inputs: R=32768, K=512, C=8
        const size_t e = ((size_t)blk * 256 + tid) * 4;
        const float4 v = *(const float4*)(inputs + e);
        const int r = (int)(e >> 9);
        const int k = (int)(e & 511);
        const int chunk = k >> 6, col = k & 63;
        __half2* d = (__half2*)&g_inc[((size_t)chunk * 32768 + r) * 64 + col];
        d[0] = __floats2half2_rn(v.x, v.y);
        d[1] = __floats2half2_rn(v.z, v.w);
    } else if (blk < 20480) {                // W_ih gate-perm: K=1024
        const size_t e = ((size_t)(blk - 16384) * 256 + tid) * 4;
        const float4 v = *(const float4*)(W_ih + e);
        const int r = (int)(e >> 10);
        const int k = (int)(e & 1023);
        const int gt = r >> 10, j = r & 1023;
        const int rp = j * 4 + gt;
        const int chunk = k >> 6, col = k & 63;
        __half2* d = (__half2*)&g_wihc[((size_t)chunk * 4096 + rp) * 64 + col];
        d[0] = __floats2half2_rn(v.x, v.y);
        d[1] = __floats2half2_rn(v.z, v.w);
    } else if (blk < 24576) {                // W_hh gate-perm
        const size_t e = ((size_t)(blk - 20480) * 256 + tid) * 4;
        const float4 v = *(const float4*)(W_hh + e);
        const int r = (int)(e >> 10);
        const int k = (int)(e & 1023);
        const int gt = r >> 10, j = r & 1023;
        const int rp = j * 4 + gt;
        const int chunk = k >> 6, col = k & 63;
        __half2* d = (__half2*)&g_whhc[((size_t)chunk * 4096 + rp) * 64 + col];
        d[0] = __floats2half2_rn(v.x, v.y);
        d[1] = __floats2half2_rn(v.z, v.w);
    } else if (blk < 25088) {                // W1: R=1024, K=512
        const size_t e = ((size_t)(blk - 24576) * 256 + tid) * 4;
        const float4 v = *(const float4*)(W1 + e);
        const int r = (int)(e >> 9);
        const int k = (int)(e & 511);
        const int chunk = k >> 6, col = k & 63;
        __half2* d = (__half2*)&g_w1c[((size_t)chunk * 1024 + r) * 64 + col];
        d[0] = __floats2half2_rn(v.x, v.y);
        d[1] = __floats2half2_rn(v.z, v.w);
    } else {                                 // setup: i in [0, B*H), scalar
        const int i = (blk - 25088) * 256 + tid;
        if (i < 2) g_bar[i] = 0;
        if (i < GG) {
            const int gt = i & 3, j = i >> 2;
            const int s = gt * HH + j;
            g_bias[i] = b_ih[s] + b_hh[s];
        }
        if (i < TT * BB) out[i] = b_out[0];
        const int b = i >> 10, j = i & 1023;
        const int chunk = j >> 6, col = j & 63;
        g_hc[((size_t)chunk * BB + b) * 64 + col] = __float2half_rn(h0[i]);
    }
}

// ===================== launch ================================================
#define SMEM_BIG 98304

extern "C" void kernel_launch(void* const* d_in, const int* in_sizes, int n_in,
                              void* d_out, int out_size)
{
    const float* inputs = (const float*)d_in[0];
    const float* h0     = (const float*)d_in[1];
    const float* c0     = (const float*)d_in[2];
    const float* W1     = (const float*)d_in[3];
    const float* b1     = (const float*)d_in[4];
    const float* W_ih   = (const float*)d_in[5];
    const float* W_hh   = (const float*)d_in[6];
    const float* b_ih   = (const float*)d_in[7];
    const float* b_hh   = (const float*)d_in[8];
    const float* W_out  = (const float*)d_in[9];
    const float* b_out  = (const float*)d_in[10];

    float* out = (float*)d_out;
    float* hT  = out + TT * BB;
    float* cT  = hT + BB * HH;

    __half *pinc, *pxc, *pw1c, *pwihc, *pwhhc, *phc, *pxg;
    float *pbias;
    cudaGetSymbolAddress((void**)&pinc,  g_inc);
    cudaGetSymbolAddress((void**)&pxc,   g_xc);
    cudaGetSymbolAddress((void**)&pw1c,  g_w1c);
    cudaGetSymbolAddress((void**)&pwihc, g_wihc);
    cudaGetSymbolAddress((void**)&pwhhc, g_whhc);
    cudaGetSymbolAddress((void**)&phc,   g_hc);
    cudaGetSymbolAddress((void**)&pxg,   g_xg);
    cudaGetSymbolAddress((void**)&pbias, g_bias);

    cudaFuncSetAttribute((const void*)gemm_mma<0>, cudaFuncAttributeMaxDynamicSharedMemorySize, SMEM_BIG);
    cudaFuncSetAttribute((const void*)gemm_mma<1>, cudaFuncAttributeMaxDynamicSharedMemorySize, SMEM_BIG);
    cudaFuncSetAttribute((const void*)rec_persist_k, cudaFuncAttributeMaxDynamicSharedMemorySize, SMEM_REC);

    // single merged conversion + setup launch (vectorized)
    prep_k<<<26112, 256>>>(inputs, W1, W_ih, W_hh, b_ih, b_hh, h0, out, b_out);

    // GEMM1: x = relu(inputs @ W1^T + b1) -> hi store g_xc  (1-pass, C=8)
    {
        dim3 grid(HH / 128, 32768 / 128);
        gemm_mma<0><<<grid, 256, SMEM_BIG>>>(pinc, pw1c, b1, nullptr, pxc, 32768, HH, 8);
    }
    // GEMM2: xg' = x_hi @ W_ih_hi'^T + bias' -> g_xg (fp16, streaming)
    {
        dim3 grid(GG / 128, 32768 / 128);
        gemm_mma<1><<<grid, 256, SMEM_BIG>>>(pxc, pwihc, pbias, pxg, nullptr, 32768, GG, 16);
    }
    // persistent recurrence: 128 co-resident CTAs, smem-resident W, 4-deep pipe
    {
        dim3 grid(GG / 64, BB / 128);
        rec_persist_k<<<grid, 256, SMEM_REC>>>(phc, phc + HSPLIT, pwhhc, pxg,
                                               W_out, c0, out, hT, cT);
    }
}